// round 8
// baseline (speedup 1.0000x reference)
#include <cuda_runtime.h>
#include <math.h>

#define BB 16
#define NAT 256
#define KNN 24
#define FF 128
#define LL 4
#define EPSC 0.01f
#define NNODE (BB*NAT)
#define NEDGE (NNODE*KNN)
#define NPB 4   // nodes per block in fused MPNN kernels

// ---------------- scratch (device globals; no allocation allowed) ----------------
__device__ float g_x[NNODE*3];
__device__ int   g_idx[NEDGE];
__device__ float g_h[NNODE*FF];
__device__ float g_y[2*NNODE*FF];    // ping-pong per-node W1 transform
__device__ float g_vec[NEDGE*3];
__device__ float g_dist[NEDGE];
__device__ float g_u[NEDGE*3];
__device__ unsigned char g_mask[NNODE*KNN*KNN];
__device__ float g_xcart[NNODE*3];
__device__ float g_strain[BB*6];   // symmetric 3x3 packed: 00,01,02,11,12,22
__device__ float g_tri[BB*6];
__device__ float g_cell[BB*9];     // geo_cell (row-major)
__device__ float g_rho[BB*9];      // action_rho
__device__ float g_invcell[BB*9];

__constant__ int c_pc[6] = {0,0,0,1,1,2};
__constant__ int c_pd[6] = {0,1,2,1,2,2};

__device__ __forceinline__ float siluf(float a) {
    return a / (1.f + expf(-a));
}

// ---------------- init: x = mod(x,1), cells = I, accumulators = 0, traj = 0 ----------------
__global__ void k_init(const float* __restrict__ x_in, float* __restrict__ out) {
    int i = blockIdx.x * blockDim.x + threadIdx.x;
    if (i < NNODE*3) { float v = x_in[i]; g_x[i] = v - floorf(v); out[i] = 0.f; }
    if (i < BB*9) {
        float id = ((i % 9) % 4 == 0) ? 1.f : 0.f;
        g_cell[i] = id; g_rho[i] = id;
    }
    if (i < BB*6) { g_strain[i] = 0.f; g_tri[i] = 0.f; }
}

// ---------------- kNN (periodic min-image, cell = I), exact top_k tie-break ----------------
__global__ void k_knn() {
    int b = blockIdx.x >> 8;
    int i = blockIdx.x & 255;
    __shared__ float sx[NAT*3];
    __shared__ float sd[NAT];
    int t = threadIdx.x;
    for (int q = t; q < NAT*3; q += 256) sx[q] = g_x[b*NAT*3 + q];
    __syncthreads();
    float xi0 = sx[i*3+0], xi1 = sx[i*3+1], xi2 = sx[i*3+2];
    float d0 = sx[t*3+0] - xi0; d0 -= rintf(d0);
    float d1 = sx[t*3+1] - xi1; d1 -= rintf(d1);
    float d2 = sx[t*3+2] - xi2; d2 -= rintf(d2);
    float d = sqrtf(d0*d0 + d1*d1 + d2*d2);
    if (t == i) d += 1e6f;
    sd[t] = d;
    __syncthreads();
    int rank = 0;
    float dt = d;
    for (int j = 0; j < NAT; j++) {
        float dj = sd[j];
        rank += (dj < dt) || (dj == dt && j < t);
    }
    if (rank < KNN) g_idx[(b*NAT + i)*KNN + rank] = t;
}

// ---------------- edge vectors: vec = (frac - round(frac)) @ cell ----------------
__global__ void k_edges() {
    int e = blockIdx.x * blockDim.x + threadIdx.x;
    if (e >= NEDGE) return;
    int b = e / (NAT*KNN);
    int n = (e / KNN) & 255;
    int j = g_idx[e];
    const float* xb = g_x + b*NAT*3;
    float f0 = xb[j*3+0] - xb[n*3+0]; f0 -= rintf(f0);
    float f1 = xb[j*3+1] - xb[n*3+1]; f1 -= rintf(f1);
    float f2 = xb[j*3+2] - xb[n*3+2]; f2 -= rintf(f2);
    const float* C = g_cell + b*9;
    float v0 = f0*C[0] + f1*C[3] + f2*C[6];
    float v1 = f0*C[1] + f1*C[4] + f2*C[7];
    float v2 = f0*C[2] + f1*C[5] + f2*C[8];
    float d  = sqrtf(v0*v0 + v1*v1 + v2*v2);
    g_vec[e*3+0] = v0; g_vec[e*3+1] = v1; g_vec[e*3+2] = v2;
    g_dist[e] = d;
    float inv = 1.f / (d + 1e-12f);
    g_u[e*3+0] = v0*inv; g_u[e*3+1] = v1*inv; g_u[e*3+2] = v2*inv;
}

// ---------------- triplet mask from INITIAL u (fixed thereafter) ----------------
__global__ void k_mask() {
    int node = blockIdx.x;
    __shared__ float su[KNN*3];
    int t = threadIdx.x;  // 64
    if (t < KNN*3) su[t] = g_u[node*KNN*3 + t];
    __syncthreads();
    for (int p = t; p < KNN*KNN; p += 64) {
        int jj = p / KNN, kk = p % KNN;
        const float* a = su + jj*3;
        const float* c = su + kk*3;
        float c0 = a[1]*c[2] - a[2]*c[1];
        float c1 = a[2]*c[0] - a[0]*c[2];
        float c2 = a[0]*c[1] - a[1]*c[0];
        g_mask[node*KNN*KNN + p] = (sqrtf(c0*c0 + c1*c1 + c2*c2) > 1e-3f) ? 1 : 0;
    }
}

// ---------------- first lin1 (NPB nodes/block): h = emb[z]; y = h @ W1[:128,:] + b1 ----------
__global__ void __launch_bounds__(128) k_lin1n(
    const float* __restrict__ W1, const float* __restrict__ b1,
    const float* __restrict__ emb, const int* __restrict__ z)
{
    int base = blockIdx.x * NPB;
    int t = threadIdx.x;
    __shared__ float shh[NPB*FF];
    #pragma unroll
    for (int m = 0; m < NPB; m++) {
        float hv = emb[z[base+m]*FF + t];
        g_h[(base+m)*FF + t] = hv;
        shh[m*FF + t] = hv;
    }
    __syncthreads();

    float acc[NPB];
    float bg = b1[t];
    #pragma unroll
    for (int m = 0; m < NPB; m++) acc[m] = bg;
    #pragma unroll 4
    for (int f = 0; f < FF; f += 4) {
        float w0 = W1[(f+0)*FF + t];
        float w1 = W1[(f+1)*FF + t];
        float w2 = W1[(f+2)*FF + t];
        float w3 = W1[(f+3)*FF + t];
        #pragma unroll
        for (int m = 0; m < NPB; m++) {
            float4 hv4 = *(const float4*)(shh + m*FF + f);
            acc[m] += hv4.x*w0 + hv4.y*w1 + hv4.z*w2 + hv4.w*w3;
        }
    }
    #pragma unroll
    for (int m = 0; m < NPB; m++) g_y[(base+m)*FF + t] = acc[m];
}

// ---------------- fused MPNN layer (NPB nodes/block): aggr -> lin2 -> h += -> lin1(next) ----
// Reads y from parity p, writes next-layer y to parity p^1 (cross-block race avoided).
__global__ void __launch_bounds__(128) k_fusedL(
    const float* __restrict__ wl_row,   // W1 row 128 (dist weights) of current layer
    const float* __restrict__ W2, const float* __restrict__ b2,
    const float* __restrict__ W1n, const float* __restrict__ b1n, int p)
{
    int base = blockIdx.x * NPB;
    int b = base >> 8;              // NPB divides 256: uniform batch per block
    int t = threadIdx.x;

    __shared__ float sdist[NPB*KNN];
    __shared__ int   sj[NPB*KNN];
    __shared__ float shm[NPB*FF];
    __shared__ float shh[NPB*FF];

    if (t < NPB*KNN) { sdist[t] = g_dist[base*KNN + t]; sj[t] = g_idx[base*KNN + t]; }
    __syncthreads();

    // aggr: msum[m] = sum_k silu(y[j_k] + dist_k * wl)
    const float* yb = g_y + p*NNODE*FF + b*NAT*FF;
    float wl = wl_row[t];
    #pragma unroll
    for (int m = 0; m < NPB; m++) {
        float s = 0.f;
        #pragma unroll 4
        for (int k = 0; k < KNN; k++) {
            float yv = yb[sj[m*KNN+k]*FF + t];
            s += siluf(yv + sdist[m*KNN+k]*wl);
        }
        shm[m*FF + t] = s;
    }
    __syncthreads();

    // lin2: h += silu(msum @ W2 + b2)
    float acc[NPB];
    float bg = b2[t];
    #pragma unroll
    for (int m = 0; m < NPB; m++) acc[m] = bg;
    #pragma unroll 4
    for (int f = 0; f < FF; f += 4) {
        float w0 = W2[(f+0)*FF + t];
        float w1 = W2[(f+1)*FF + t];
        float w2 = W2[(f+2)*FF + t];
        float w3 = W2[(f+3)*FF + t];
        #pragma unroll
        for (int m = 0; m < NPB; m++) {
            float4 mv = *(const float4*)(shm + m*FF + f);
            acc[m] += mv.x*w0 + mv.y*w1 + mv.z*w2 + mv.w*w3;
        }
    }
    #pragma unroll
    for (int m = 0; m < NPB; m++) {
        float hn = g_h[(base+m)*FF + t] + siluf(acc[m]);
        g_h[(base+m)*FF + t] = hn;
        shh[m*FF + t] = hn;
    }

    // lin1 of next layer (node-local h)
    if (W1n) {
        __syncthreads();
        float bg1 = b1n[t];
        #pragma unroll
        for (int m = 0; m < NPB; m++) acc[m] = bg1;
        #pragma unroll 4
        for (int f = 0; f < FF; f += 4) {
            float w0 = W1n[(f+0)*FF + t];
            float w1 = W1n[(f+1)*FF + t];
            float w2 = W1n[(f+2)*FF + t];
            float w3 = W1n[(f+3)*FF + t];
            #pragma unroll
            for (int m = 0; m < NPB; m++) {
                float4 hv4 = *(const float4*)(shh + m*FF + f);
                acc[m] += hv4.x*w0 + hv4.y*w1 + hv4.z*w2 + hv4.w*w3;
            }
        }
        #pragma unroll
        for (int m = 0; m < NPB; m++)
            g_y[(p^1)*NNODE*FF + (base+m)*FF + t] = acc[m];
    }
}

// ---------------- edge weights + strain/tri partials + x_cart ----------------
__global__ void __launch_bounds__(128) k_edgew(
    const float* __restrict__ awe, const float* __restrict__ awp)
{
    const float* h = g_h;
    int node = blockIdx.x;
    int b = node >> 8;
    int t = threadIdx.x;
    int lane = t & 31, w = t >> 5;

    __shared__ float sh_hi[FF], sh_awe[FF], sh_awp[FF];
    __shared__ float sh_we[KNN], sh_wp[KNN];
    __shared__ float su[KNN*3], sv[KNN*3];
    __shared__ float sT[6];

    sh_hi[t]  = h[node*FF + t];
    sh_awe[t] = awe[t];
    sh_awp[t] = awp[t];
    if (t < KNN*3) { su[t] = g_u[node*KNN*3 + t]; sv[t] = g_vec[node*KNN*3 + t]; }
    if (t < 6) sT[t] = 0.f;
    __syncthreads();

    // w_e, w_p : each warp handles 6 edges, 32-lane dot over F
    #pragma unroll
    for (int q = 0; q < 6; q++) {
        int k = w*6 + q;
        int j = g_idx[node*KNN + k];
        const float* hj = h + (b*NAT + j)*FF;
        float de = 0.f, dp = 0.f;
        #pragma unroll
        for (int m = 0; m < 4; m++) {
            int f = lane + 32*m;
            float e = sh_hi[f] + hj[f];
            de += e * sh_awe[f];
            dp += e * sh_awp[f];
        }
        #pragma unroll
        for (int o = 16; o; o >>= 1) {
            de += __shfl_xor_sync(0xffffffffu, de, o);
            dp += __shfl_xor_sync(0xffffffffu, dp, o);
        }
        if (lane == 0) { sh_we[k] = tanhf(de); sh_wp[k] = tanhf(dp); }
    }
    __syncthreads();

    // strain partial (symmetric 6) and x_cart
    if (t < 6) {
        int c = c_pc[t], d = c_pd[t];
        float s = 0.f;
        #pragma unroll
        for (int k = 0; k < KNN; k++) s += sh_we[k] * su[k*3+c] * su[k*3+d];
        atomicAdd(&g_strain[b*6 + t], s);
    } else if (t >= 16 && t < 19) {
        int c = t - 16;
        float s = 0.f;
        #pragma unroll
        for (int k = 0; k < KNN; k++) s += sh_wp[k] * sv[k*3+c];
        g_xcart[node*3 + c] = EPSC * s;
    }

    // tri partial over 576 pairs (cross products on the fly, symmetric 6)
    float T0=0.f,T1=0.f,T2=0.f,T3=0.f,T4=0.f,T5=0.f;
    const unsigned char* mp = g_mask + node*KNN*KNN;
    for (int p = t; p < KNN*KNN; p += 128) {
        if (!mp[p]) continue;
        int jj = p / KNN, kk = p - jj*KNN;
        float wjk = sh_we[jj] * sh_we[kk];
        const float* a = su + jj*3;
        const float* c = su + kk*3;
        float c0 = a[1]*c[2] - a[2]*c[1];
        float c1 = a[2]*c[0] - a[0]*c[2];
        float c2 = a[0]*c[1] - a[1]*c[0];
        T0 += wjk*c0*c0; T1 += wjk*c0*c1; T2 += wjk*c0*c2;
        T3 += wjk*c1*c1; T4 += wjk*c1*c2; T5 += wjk*c2*c2;
    }
    #pragma unroll
    for (int o = 16; o; o >>= 1) {
        T0 += __shfl_xor_sync(0xffffffffu, T0, o);
        T1 += __shfl_xor_sync(0xffffffffu, T1, o);
        T2 += __shfl_xor_sync(0xffffffffu, T2, o);
        T3 += __shfl_xor_sync(0xffffffffu, T3, o);
        T4 += __shfl_xor_sync(0xffffffffu, T4, o);
        T5 += __shfl_xor_sync(0xffffffffu, T5, o);
    }
    if (lane == 0) {
        atomicAdd(&sT[0], T0); atomicAdd(&sT[1], T1); atomicAdd(&sT[2], T2);
        atomicAdd(&sT[3], T3); atomicAdd(&sT[4], T4); atomicAdd(&sT[5], T5);
    }
    __syncthreads();
    if (t < 6) atomicAdd(&g_tri[b*6 + t], sT[t]);
}

// ---------------- per-batch action update; inv(old cell); zero accumulators ----------------
__global__ void k_action(int is_last, float* __restrict__ out) {
    int b = blockIdx.x;
    if (threadIdx.x != 0) return;
    float s6[6], t6[6];
    #pragma unroll
    for (int i = 0; i < 6; i++) {
        s6[i] = g_strain[b*6+i]; t6[i] = g_tri[b*6+i];
        g_strain[b*6+i] = 0.f;   g_tri[b*6+i] = 0.f;
    }
    const float NK  = (float)(NAT*KNN);
    const float NKK = (float)(NAT*KNN*KNN);
    float P[9];
    P[0] = s6[0]/NK + t6[0]/NKK;
    P[1] = s6[1]/NK + t6[1]/NKK; P[3] = P[1];
    P[2] = s6[2]/NK + t6[2]/NKK; P[6] = P[2];
    P[4] = s6[3]/NK + t6[3]/NKK;
    P[5] = s6[4]/NK + t6[4]/NKK; P[7] = P[5];
    P[8] = s6[5]/NK + t6[5]/NKK;
    float A[9];
    #pragma unroll
    for (int i = 0; i < 9; i++) A[i] = EPSC*P[i] + ((i % 4 == 0) ? 1.f : 0.f);
    float R[9], C[9], Rn[9];
    #pragma unroll
    for (int i = 0; i < 9; i++) { R[i] = g_rho[b*9+i]; C[i] = g_cell[b*9+i]; }
    #pragma unroll
    for (int i = 0; i < 3; i++)
        #pragma unroll
        for (int k = 0; k < 3; k++)
            Rn[i*3+k] = A[i*3+0]*R[0+k] + A[i*3+1]*R[3+k] + A[i*3+2]*R[6+k];
    // inverse of OLD geo_cell (adjugate)
    float det = C[0]*(C[4]*C[8]-C[5]*C[7]) - C[1]*(C[3]*C[8]-C[5]*C[6]) + C[2]*(C[3]*C[7]-C[4]*C[6]);
    float id = 1.f/det;
    float IV[9];
    IV[0]=(C[4]*C[8]-C[5]*C[7])*id;
    IV[1]=(C[2]*C[7]-C[1]*C[8])*id;
    IV[2]=(C[1]*C[5]-C[2]*C[4])*id;
    IV[3]=(C[5]*C[6]-C[3]*C[8])*id;
    IV[4]=(C[0]*C[8]-C[2]*C[6])*id;
    IV[5]=(C[2]*C[3]-C[0]*C[5])*id;
    IV[6]=(C[3]*C[7]-C[4]*C[6])*id;
    IV[7]=(C[1]*C[6]-C[0]*C[7])*id;
    IV[8]=(C[0]*C[4]-C[1]*C[3])*id;
    #pragma unroll
    for (int i = 0; i < 9; i++) {
        g_invcell[b*9+i] = IV[i];
        g_rho[b*9+i] = Rn[i];
        g_cell[b*9+i] = Rn[i];   // geo_cell = rho_prime (cell0 = I)
    }
    if (is_last) {
        #pragma unroll
        for (int i = 0; i < 9; i++) out[NNODE*3 + b*9 + i] = Rn[i];
    }
}

// ---------------- position update: x += x_cart @ inv(old cell); traj += x_cart ----------------
__global__ void k_pos(float* __restrict__ out) {
    int node = blockIdx.x * blockDim.x + threadIdx.x;
    if (node >= NNODE) return;
    int b = node >> 8;
    float xc0 = g_xcart[node*3+0];
    float xc1 = g_xcart[node*3+1];
    float xc2 = g_xcart[node*3+2];
    const float* iv = g_invcell + b*9;
    float xf0 = xc0*iv[0] + xc1*iv[3] + xc2*iv[6];
    float xf1 = xc0*iv[1] + xc1*iv[4] + xc2*iv[7];
    float xf2 = xc0*iv[2] + xc1*iv[5] + xc2*iv[8];
    g_x[node*3+0] += xf0;
    g_x[node*3+1] += xf1;
    g_x[node*3+2] += xf2;
    out[node*3+0] += xc0;
    out[node*3+1] += xc1;
    out[node*3+2] += xc2;
}

// ---------------- launch ----------------
extern "C" void kernel_launch(void* const* d_in, const int* in_sizes, int n_in,
                              void* d_out, int out_size) {
    const float* x_in = (const float*)d_in[1];
    const int*   z    = (const int*)  d_in[2];
    const float* emb  = (const float*)d_in[4];
    const float* mW1  = (const float*)d_in[5];
    const float* mb1  = (const float*)d_in[6];
    const float* mW2  = (const float*)d_in[7];
    const float* mb2  = (const float*)d_in[8];
    const float* uW1  = (const float*)d_in[9];
    const float* ub1  = (const float*)d_in[10];
    const float* uW2  = (const float*)d_in[11];
    const float* ub2  = (const float*)d_in[12];
    const float* awe  = (const float*)d_in[13];
    const float* awp  = (const float*)d_in[14];
    float* out = (float*)d_out;

    const int SZ1 = (FF+1)*FF;
    const int NGB = NNODE / NPB;   // 1024 blocks

    k_init <<<48, 256>>>(x_in, out);
    k_knn  <<<NNODE, 256>>>();
    k_edges<<<(NEDGE + 255)/256, 256>>>();
    k_mask <<<NNODE, 64>>>();

    k_lin1n<<<NGB, 128>>>(mW1, mb1, emb, z);
    int p = 0;
    for (int l = 0; l < LL; l++) {
        const float* W1n = (l < 3) ? (mW1 + (l+1)*SZ1) : uW1;
        const float* b1n = (l < 3) ? (mb1 + (l+1)*FF)  : ub1;
        k_fusedL<<<NGB, 128>>>(mW1 + l*SZ1 + FF*FF, mW2 + l*FF*FF, mb2 + l*FF, W1n, b1n, p);
        p ^= 1;
    }
    for (int l = 0; l < LL; l++) {
        const float* W1n = (l < 3) ? (uW1 + (l+1)*SZ1) : (const float*)0;
        const float* b1n = (l < 3) ? (ub1 + (l+1)*FF)  : (const float*)0;
        k_fusedL<<<NGB, 128>>>(uW1 + l*SZ1 + FF*FF, uW2 + l*FF*FF, ub2 + l*FF, W1n, b1n, p);
        p ^= 1;
        k_edgew<<<NNODE, 128>>>(awe + l*FF, awp + l*FF);
        k_action<<<BB, 32>>>(l == LL-1 ? 1 : 0, out);
        k_pos  <<<(NNODE + 255)/256, 256>>>(out);
        if (l < LL-1) k_edges<<<(NEDGE + 255)/256, 256>>>();
    }
}

// round 10
// speedup vs baseline: 1.0705x; 1.0705x over previous
#include <cuda_runtime.h>
#include <math.h>

#define BB 16
#define NAT 256
#define KNN 24
#define FF 128
#define LL 4
#define EPSC 0.01f
#define NNODE (BB*NAT)
#define NEDGE (NNODE*KNN)

// ---------------- scratch (device globals; no allocation allowed) ----------------
__device__ float g_x[NNODE*3];
__device__ int   g_idx[NEDGE];
__device__ float g_h[NNODE*FF];
__device__ float g_y[2*NNODE*FF];    // ping-pong per-node W1 transform
__device__ float g_vec[NEDGE*3];
__device__ float g_dist[NEDGE];
__device__ float g_u[NEDGE*3];
__device__ unsigned char g_mask[NNODE*KNN*KNN];
__device__ float g_xcart[NNODE*3];
__device__ float g_strain[BB*6];   // symmetric 3x3 packed: 00,01,02,11,12,22
__device__ float g_tri[BB*6];
__device__ float g_cell[BB*9];     // geo_cell (row-major)
__device__ float g_rho[BB*9];      // action_rho

__constant__ int c_pc[6] = {0,0,0,1,1,2};
__constant__ int c_pd[6] = {0,1,2,1,2,2};

__device__ __forceinline__ float siluf(float a) {
    return a / (1.f + expf(-a));
}

// ---------------- init: x = mod(x,1), cells = I, accumulators = 0, traj = 0 ----------------
__global__ void k_init(const float* __restrict__ x_in, float* __restrict__ out) {
    int i = blockIdx.x * blockDim.x + threadIdx.x;
    if (i < NNODE*3) { float v = x_in[i]; g_x[i] = v - floorf(v); out[i] = 0.f; }
    if (i < BB*9) {
        float id = ((i % 9) % 4 == 0) ? 1.f : 0.f;
        g_cell[i] = id; g_rho[i] = id;
    }
    if (i < BB*6) { g_strain[i] = 0.f; g_tri[i] = 0.f; }
}

// ---------------- kNN (periodic min-image, cell = I), exact top_k tie-break ----------------
__global__ void k_knn() {
    int b = blockIdx.x >> 8;
    int i = blockIdx.x & 255;
    __shared__ float sx[NAT*3];
    __shared__ float sd[NAT];
    int t = threadIdx.x;
    for (int q = t; q < NAT*3; q += 256) sx[q] = g_x[b*NAT*3 + q];
    __syncthreads();
    float xi0 = sx[i*3+0], xi1 = sx[i*3+1], xi2 = sx[i*3+2];
    float d0 = sx[t*3+0] - xi0; d0 -= rintf(d0);
    float d1 = sx[t*3+1] - xi1; d1 -= rintf(d1);
    float d2 = sx[t*3+2] - xi2; d2 -= rintf(d2);
    float d = sqrtf(d0*d0 + d1*d1 + d2*d2);
    if (t == i) d += 1e6f;
    sd[t] = d;
    __syncthreads();
    int rank = 0;
    float dt = d;
    for (int j = 0; j < NAT; j++) {
        float dj = sd[j];
        rank += (dj < dt) || (dj == dt && j < t);
    }
    if (rank < KNN) g_idx[(b*NAT + i)*KNN + rank] = t;
}

// ---------------- initial edge vectors: vec = (frac - round(frac)) @ cell ----------------
__global__ void k_edges() {
    int e = blockIdx.x * blockDim.x + threadIdx.x;
    if (e >= NEDGE) return;
    int b = e / (NAT*KNN);
    int n = (e / KNN) & 255;
    int j = g_idx[e];
    const float* xb = g_x + b*NAT*3;
    float f0 = xb[j*3+0] - xb[n*3+0]; f0 -= rintf(f0);
    float f1 = xb[j*3+1] - xb[n*3+1]; f1 -= rintf(f1);
    float f2 = xb[j*3+2] - xb[n*3+2]; f2 -= rintf(f2);
    const float* C = g_cell + b*9;
    float v0 = f0*C[0] + f1*C[3] + f2*C[6];
    float v1 = f0*C[1] + f1*C[4] + f2*C[7];
    float v2 = f0*C[2] + f1*C[5] + f2*C[8];
    float d  = sqrtf(v0*v0 + v1*v1 + v2*v2);
    g_vec[e*3+0] = v0; g_vec[e*3+1] = v1; g_vec[e*3+2] = v2;
    g_dist[e] = d;
    float inv = 1.f / (d + 1e-12f);
    g_u[e*3+0] = v0*inv; g_u[e*3+1] = v1*inv; g_u[e*3+2] = v2*inv;
}

// ---------------- triplet mask from INITIAL u (fixed thereafter) ----------------
__global__ void k_mask() {
    int node = blockIdx.x;
    __shared__ float su[KNN*3];
    int t = threadIdx.x;  // 64
    if (t < KNN*3) su[t] = g_u[node*KNN*3 + t];
    __syncthreads();
    for (int p = t; p < KNN*KNN; p += 64) {
        int jj = p / KNN, kk = p % KNN;
        const float* a = su + jj*3;
        const float* c = su + kk*3;
        float c0 = a[1]*c[2] - a[2]*c[1];
        float c1 = a[2]*c[0] - a[0]*c[2];
        float c2 = a[0]*c[1] - a[1]*c[0];
        g_mask[node*KNN*KNN + p] = (sqrtf(c0*c0 + c1*c1 + c2*c2) > 1e-3f) ? 1 : 0;
    }
}

// ---------------- first lin1 (per node): h = emb[z]; y = h @ W1[:128,:] + b1 ----------------
__global__ void __launch_bounds__(128) k_lin1n(
    const float* __restrict__ W1, const float* __restrict__ b1,
    const float* __restrict__ emb, const int* __restrict__ z)
{
    int node = blockIdx.x;
    int t = threadIdx.x;
    __shared__ float shh[FF];
    float hv = emb[z[node]*FF + t];
    g_h[node*FF + t] = hv;
    shh[t] = hv;
    __syncthreads();

    float acc = b1[t];
    #pragma unroll 4
    for (int f = 0; f < FF; f += 4) {
        float w0 = W1[(f+0)*FF + t];
        float w1 = W1[(f+1)*FF + t];
        float w2 = W1[(f+2)*FF + t];
        float w3 = W1[(f+3)*FF + t];
        float4 hv4 = *(const float4*)(shh + f);
        acc += hv4.x*w0 + hv4.y*w1 + hv4.z*w2 + hv4.w*w3;
    }
    g_y[node*FF + t] = acc;
}

// ---------------- fused MPNN layer (per node): aggr -> lin2 -> h += -> lin1(next) ----------
// Reads y from parity p, writes next-layer y to parity p^1 (cross-block race avoided).
__global__ void __launch_bounds__(128) k_fusedL(
    const float* __restrict__ wl_row,   // W1 row 128 (dist weights) of current layer
    const float* __restrict__ W2, const float* __restrict__ b2,
    const float* __restrict__ W1n, const float* __restrict__ b1n, int p)
{
    int node = blockIdx.x;
    int b = node >> 8;
    int t = threadIdx.x;

    __shared__ float sdist[KNN];
    __shared__ int   sj[KNN];
    __shared__ float shm[FF];
    __shared__ float shh[FF];

    if (t < KNN) { sdist[t] = g_dist[node*KNN + t]; sj[t] = g_idx[node*KNN + t]; }
    __syncthreads();

    // aggr: msum = sum_k silu(y[j_k] + dist_k * wl)
    const float* yb = g_y + p*NNODE*FF + b*NAT*FF;
    float wl = wl_row[t];
    float s = 0.f;
    #pragma unroll 4
    for (int k = 0; k < KNN; k++) {
        float yv = yb[sj[k]*FF + t];
        s += siluf(yv + sdist[k]*wl);
    }
    shm[t] = s;
    __syncthreads();

    // lin2: h += silu(msum @ W2 + b2)
    float acc = b2[t];
    #pragma unroll 4
    for (int f = 0; f < FF; f += 4) {
        float w0 = W2[(f+0)*FF + t];
        float w1 = W2[(f+1)*FF + t];
        float w2 = W2[(f+2)*FF + t];
        float w3 = W2[(f+3)*FF + t];
        float4 mv = *(const float4*)(shm + f);
        acc += mv.x*w0 + mv.y*w1 + mv.z*w2 + mv.w*w3;
    }
    float hn = g_h[node*FF + t] + siluf(acc);
    g_h[node*FF + t] = hn;

    // lin1 of next layer (node-local h)
    if (W1n) {
        shh[t] = hn;
        __syncthreads();
        float a1 = b1n[t];
        #pragma unroll 4
        for (int f = 0; f < FF; f += 4) {
            float w0 = W1n[(f+0)*FF + t];
            float w1 = W1n[(f+1)*FF + t];
            float w2 = W1n[(f+2)*FF + t];
            float w3 = W1n[(f+3)*FF + t];
            float4 hv4 = *(const float4*)(shh + f);
            a1 += hv4.x*w0 + hv4.y*w1 + hv4.z*w2 + hv4.w*w3;
        }
        g_y[(p^1)*NNODE*FF + node*FF + t] = a1;
    }
}

// ---------------- edge weights + strain/tri partials + x_cart ----------------
__global__ void __launch_bounds__(128) k_edgew(
    const float* __restrict__ awe, const float* __restrict__ awp)
{
    const float* h = g_h;
    int node = blockIdx.x;
    int b = node >> 8;
    int t = threadIdx.x;
    int lane = t & 31, w = t >> 5;

    __shared__ float sh_hi[FF], sh_awe[FF], sh_awp[FF];
    __shared__ float sh_we[KNN], sh_wp[KNN];
    __shared__ float su[KNN*3], sv[KNN*3];
    __shared__ float sT[6];

    sh_hi[t]  = h[node*FF + t];
    sh_awe[t] = awe[t];
    sh_awp[t] = awp[t];
    if (t < KNN*3) { su[t] = g_u[node*KNN*3 + t]; sv[t] = g_vec[node*KNN*3 + t]; }
    if (t < 6) sT[t] = 0.f;
    __syncthreads();

    // w_e, w_p : each warp handles 6 edges, 32-lane dot over F
    #pragma unroll
    for (int q = 0; q < 6; q++) {
        int k = w*6 + q;
        int j = g_idx[node*KNN + k];
        const float* hj = h + (b*NAT + j)*FF;
        float de = 0.f, dp = 0.f;
        #pragma unroll
        for (int m = 0; m < 4; m++) {
            int f = lane + 32*m;
            float e = sh_hi[f] + hj[f];
            de += e * sh_awe[f];
            dp += e * sh_awp[f];
        }
        #pragma unroll
        for (int o = 16; o; o >>= 1) {
            de += __shfl_xor_sync(0xffffffffu, de, o);
            dp += __shfl_xor_sync(0xffffffffu, dp, o);
        }
        if (lane == 0) { sh_we[k] = tanhf(de); sh_wp[k] = tanhf(dp); }
    }
    __syncthreads();

    // strain partial (symmetric 6) and x_cart
    if (t < 6) {
        int c = c_pc[t], d = c_pd[t];
        float s = 0.f;
        #pragma unroll
        for (int k = 0; k < KNN; k++) s += sh_we[k] * su[k*3+c] * su[k*3+d];
        atomicAdd(&g_strain[b*6 + t], s);
    } else if (t >= 16 && t < 19) {
        int c = t - 16;
        float s = 0.f;
        #pragma unroll
        for (int k = 0; k < KNN; k++) s += sh_wp[k] * sv[k*3+c];
        g_xcart[node*3 + c] = EPSC * s;
    }

    // tri partial over 576 pairs (cross products on the fly, symmetric 6)
    float T0=0.f,T1=0.f,T2=0.f,T3=0.f,T4=0.f,T5=0.f;
    const unsigned char* mp = g_mask + node*KNN*KNN;
    for (int p = t; p < KNN*KNN; p += 128) {
        if (!mp[p]) continue;
        int jj = p / KNN, kk = p - jj*KNN;
        float wjk = sh_we[jj] * sh_we[kk];
        const float* a = su + jj*3;
        const float* c = su + kk*3;
        float c0 = a[1]*c[2] - a[2]*c[1];
        float c1 = a[2]*c[0] - a[0]*c[2];
        float c2 = a[0]*c[1] - a[1]*c[0];
        T0 += wjk*c0*c0; T1 += wjk*c0*c1; T2 += wjk*c0*c2;
        T3 += wjk*c1*c1; T4 += wjk*c1*c2; T5 += wjk*c2*c2;
    }
    #pragma unroll
    for (int o = 16; o; o >>= 1) {
        T0 += __shfl_xor_sync(0xffffffffu, T0, o);
        T1 += __shfl_xor_sync(0xffffffffu, T1, o);
        T2 += __shfl_xor_sync(0xffffffffu, T2, o);
        T3 += __shfl_xor_sync(0xffffffffu, T3, o);
        T4 += __shfl_xor_sync(0xffffffffu, T4, o);
        T5 += __shfl_xor_sync(0xffffffffu, T5, o);
    }
    if (lane == 0) {
        atomicAdd(&sT[0], T0); atomicAdd(&sT[1], T1); atomicAdd(&sT[2], T2);
        atomicAdd(&sT[3], T3); atomicAdd(&sT[4], T4); atomicAdd(&sT[5], T5);
    }
    __syncthreads();
    if (t < 6) atomicAdd(&g_tri[b*6 + t], sT[t]);
}

// ---------------- fused tail: action + position update + edge recompute (one block/batch) ----
__global__ void __launch_bounds__(256) k_tail(int is_last, float* __restrict__ out)
{
    int b = blockIdx.x;
    int t = threadIdx.x;   // 256 = NAT

    __shared__ float s_iv[9];     // inv(old geo_cell)
    __shared__ float s_cell[9];   // new geo_cell = rho_prime
    __shared__ float sx[NAT*3];   // updated fractional positions

    if (t == 0) {
        float s6[6], t6[6];
        #pragma unroll
        for (int i = 0; i < 6; i++) {
            s6[i] = g_strain[b*6+i]; t6[i] = g_tri[b*6+i];
            g_strain[b*6+i] = 0.f;   g_tri[b*6+i] = 0.f;
        }
        const float NK  = (float)(NAT*KNN);
        const float NKK = (float)(NAT*KNN*KNN);
        float P[9];
        P[0] = s6[0]/NK + t6[0]/NKK;
        P[1] = s6[1]/NK + t6[1]/NKK; P[3] = P[1];
        P[2] = s6[2]/NK + t6[2]/NKK; P[6] = P[2];
        P[4] = s6[3]/NK + t6[3]/NKK;
        P[5] = s6[4]/NK + t6[4]/NKK; P[7] = P[5];
        P[8] = s6[5]/NK + t6[5]/NKK;
        float A[9];
        #pragma unroll
        for (int i = 0; i < 9; i++) A[i] = EPSC*P[i] + ((i % 4 == 0) ? 1.f : 0.f);
        float R[9], C[9], Rn[9];
        #pragma unroll
        for (int i = 0; i < 9; i++) { R[i] = g_rho[b*9+i]; C[i] = g_cell[b*9+i]; }
        #pragma unroll
        for (int i = 0; i < 3; i++)
            #pragma unroll
            for (int k = 0; k < 3; k++)
                Rn[i*3+k] = A[i*3+0]*R[0+k] + A[i*3+1]*R[3+k] + A[i*3+2]*R[6+k];
        // inverse of OLD geo_cell (adjugate)
        float det = C[0]*(C[4]*C[8]-C[5]*C[7]) - C[1]*(C[3]*C[8]-C[5]*C[6]) + C[2]*(C[3]*C[7]-C[4]*C[6]);
        float id = 1.f/det;
        s_iv[0]=(C[4]*C[8]-C[5]*C[7])*id;
        s_iv[1]=(C[2]*C[7]-C[1]*C[8])*id;
        s_iv[2]=(C[1]*C[5]-C[2]*C[4])*id;
        s_iv[3]=(C[5]*C[6]-C[3]*C[8])*id;
        s_iv[4]=(C[0]*C[8]-C[2]*C[6])*id;
        s_iv[5]=(C[2]*C[3]-C[0]*C[5])*id;
        s_iv[6]=(C[3]*C[7]-C[4]*C[6])*id;
        s_iv[7]=(C[1]*C[6]-C[0]*C[7])*id;
        s_iv[8]=(C[0]*C[4]-C[1]*C[3])*id;
        #pragma unroll
        for (int i = 0; i < 9; i++) {
            s_cell[i] = Rn[i];
            g_rho[b*9+i] = Rn[i];
            g_cell[b*9+i] = Rn[i];   // geo_cell = rho_prime (cell0 = I)
        }
        if (is_last) {
            #pragma unroll
            for (int i = 0; i < 9; i++) out[NNODE*3 + b*9 + i] = Rn[i];
        }
    }
    __syncthreads();

    // position update for node b*NAT + t
    int node = b*NAT + t;
    {
        float xc0 = g_xcart[node*3+0];
        float xc1 = g_xcart[node*3+1];
        float xc2 = g_xcart[node*3+2];
        float xf0 = xc0*s_iv[0] + xc1*s_iv[3] + xc2*s_iv[6];
        float xf1 = xc0*s_iv[1] + xc1*s_iv[4] + xc2*s_iv[7];
        float xf2 = xc0*s_iv[2] + xc1*s_iv[5] + xc2*s_iv[8];
        float x0 = g_x[node*3+0] + xf0;
        float x1 = g_x[node*3+1] + xf1;
        float x2 = g_x[node*3+2] + xf2;
        g_x[node*3+0] = x0; g_x[node*3+1] = x1; g_x[node*3+2] = x2;
        sx[t*3+0] = x0; sx[t*3+1] = x1; sx[t*3+2] = x2;
        out[node*3+0] += xc0;
        out[node*3+1] += xc1;
        out[node*3+2] += xc2;
    }
    __syncthreads();

    // edge recompute for this batch (6144 edges, 24 per thread)
    if (!is_last) {
        for (int q = t; q < NAT*KNN; q += 256) {
            int e = b*NAT*KNN + q;
            int n = q / KNN;
            int j = g_idx[e];
            float f0 = sx[j*3+0] - sx[n*3+0]; f0 -= rintf(f0);
            float f1 = sx[j*3+1] - sx[n*3+1]; f1 -= rintf(f1);
            float f2 = sx[j*3+2] - sx[n*3+2]; f2 -= rintf(f2);
            float v0 = f0*s_cell[0] + f1*s_cell[3] + f2*s_cell[6];
            float v1 = f0*s_cell[1] + f1*s_cell[4] + f2*s_cell[7];
            float v2 = f0*s_cell[2] + f1*s_cell[5] + f2*s_cell[8];
            float d  = sqrtf(v0*v0 + v1*v1 + v2*v2);
            g_vec[e*3+0] = v0; g_vec[e*3+1] = v1; g_vec[e*3+2] = v2;
            g_dist[e] = d;
            float inv = 1.f / (d + 1e-12f);
            g_u[e*3+0] = v0*inv; g_u[e*3+1] = v1*inv; g_u[e*3+2] = v2*inv;
        }
    }
}

// ---------------- launch ----------------
extern "C" void kernel_launch(void* const* d_in, const int* in_sizes, int n_in,
                              void* d_out, int out_size) {
    const float* x_in = (const float*)d_in[1];
    const int*   z    = (const int*)  d_in[2];
    const float* emb  = (const float*)d_in[4];
    const float* mW1  = (const float*)d_in[5];
    const float* mb1  = (const float*)d_in[6];
    const float* mW2  = (const float*)d_in[7];
    const float* mb2  = (const float*)d_in[8];
    const float* uW1  = (const float*)d_in[9];
    const float* ub1  = (const float*)d_in[10];
    const float* uW2  = (const float*)d_in[11];
    const float* ub2  = (const float*)d_in[12];
    const float* awe  = (const float*)d_in[13];
    const float* awp  = (const float*)d_in[14];
    float* out = (float*)d_out;

    const int SZ1 = (FF+1)*FF;

    k_init <<<48, 256>>>(x_in, out);
    k_knn  <<<NNODE, 256>>>();
    k_edges<<<(NEDGE + 255)/256, 256>>>();
    k_mask <<<NNODE, 64>>>();

    k_lin1n<<<NNODE, 128>>>(mW1, mb1, emb, z);
    int p = 0;
    for (int l = 0; l < LL; l++) {
        const float* W1n = (l < 3) ? (mW1 + (l+1)*SZ1) : uW1;
        const float* b1n = (l < 3) ? (mb1 + (l+1)*FF)  : ub1;
        k_fusedL<<<NNODE, 128>>>(mW1 + l*SZ1 + FF*FF, mW2 + l*FF*FF, mb2 + l*FF, W1n, b1n, p);
        p ^= 1;
    }
    for (int l = 0; l < LL; l++) {
        const float* W1n = (l < 3) ? (uW1 + (l+1)*SZ1) : (const float*)0;
        const float* b1n = (l < 3) ? (ub1 + (l+1)*FF)  : (const float*)0;
        k_fusedL<<<NNODE, 128>>>(uW1 + l*SZ1 + FF*FF, uW2 + l*FF*FF, ub2 + l*FF, W1n, b1n, p);
        p ^= 1;
        k_edgew<<<NNODE, 128>>>(awe + l*FF, awp + l*FF);
        k_tail <<<BB, 256>>>(l == LL-1 ? 1 : 0, out);
    }
}

// round 11
// speedup vs baseline: 1.1406x; 1.0655x over previous
#include <cuda_runtime.h>
#include <math.h>

#define BB 16
#define NAT 256
#define KNN 24
#define FF 128
#define LL 4
#define EPSC 0.01f
#define NNODE (BB*NAT)
#define NEDGE (NNODE*KNN)

// ---------------- scratch (device globals; no allocation allowed) ----------------
__device__ float g_x[NNODE*3];
__device__ int   g_idx[NEDGE];
__device__ float g_h[NNODE*FF];
__device__ float g_y[2*NNODE*FF];    // ping-pong per-node W1 transform
__device__ float g_de[NNODE];        // per-node dot(h, act_we)
__device__ float g_dp[NNODE];        // per-node dot(h, actpos_we)
__device__ float g_vec[NEDGE*3];
__device__ float g_dist[NEDGE];
__device__ float g_u[NEDGE*3];
__device__ unsigned char g_mask[NNODE*KNN*KNN];
__device__ float g_xcart[NNODE*3];
__device__ float g_strain[BB*6];   // symmetric 3x3 packed: 00,01,02,11,12,22
__device__ float g_tri[BB*6];
__device__ float g_cell[BB*9];     // geo_cell (row-major)
__device__ float g_rho[BB*9];      // action_rho
__device__ float g_invcell[BB*9];

__constant__ int c_pc[6] = {0,0,0,1,1,2};
__constant__ int c_pd[6] = {0,1,2,1,2,2};

__device__ __forceinline__ float siluf(float a) {
    return a / (1.f + expf(-a));
}

// ---------------- init: x = mod(x,1), cells = I, accumulators = 0, traj = 0 ----------------
__global__ void k_init(const float* __restrict__ x_in, float* __restrict__ out) {
    int i = blockIdx.x * blockDim.x + threadIdx.x;
    if (i < NNODE*3) { float v = x_in[i]; g_x[i] = v - floorf(v); out[i] = 0.f; }
    if (i < BB*9) {
        float id = ((i % 9) % 4 == 0) ? 1.f : 0.f;
        g_cell[i] = id; g_rho[i] = id;
    }
    if (i < BB*6) { g_strain[i] = 0.f; g_tri[i] = 0.f; }
}

// ---------------- kNN (periodic min-image, cell = I), exact top_k tie-break ----------------
__global__ void k_knn() {
    int b = blockIdx.x >> 8;
    int i = blockIdx.x & 255;
    __shared__ float sx[NAT*3];
    __shared__ __align__(16) float sd[NAT];
    int t = threadIdx.x;
    for (int q = t; q < NAT*3; q += 256) sx[q] = g_x[b*NAT*3 + q];
    __syncthreads();
    float xi0 = sx[i*3+0], xi1 = sx[i*3+1], xi2 = sx[i*3+2];
    float d0 = sx[t*3+0] - xi0; d0 -= rintf(d0);
    float d1 = sx[t*3+1] - xi1; d1 -= rintf(d1);
    float d2 = sx[t*3+2] - xi2; d2 -= rintf(d2);
    float d = sqrtf(d0*d0 + d1*d1 + d2*d2);
    if (t == i) d += 1e6f;
    sd[t] = d;
    __syncthreads();
    int rank = 0;
    float dt = d;
    const float4* sd4 = (const float4*)sd;
    #pragma unroll 8
    for (int q = 0; q < NAT/4; q++) {
        float4 v = sd4[q];
        int j0 = q*4;
        rank += (v.x < dt) || (v.x == dt && (j0+0) < t);
        rank += (v.y < dt) || (v.y == dt && (j0+1) < t);
        rank += (v.z < dt) || (v.z == dt && (j0+2) < t);
        rank += (v.w < dt) || (v.w == dt && (j0+3) < t);
    }
    if (rank < KNN) g_idx[(b*NAT + i)*KNN + rank] = t;
}

// ---------------- initial edge vectors: vec = (frac - round(frac)) @ cell ----------------
__global__ void k_edges() {
    int e = blockIdx.x * blockDim.x + threadIdx.x;
    if (e >= NEDGE) return;
    int b = e / (NAT*KNN);
    int n = (e / KNN) & 255;
    int j = g_idx[e];
    const float* xb = g_x + b*NAT*3;
    float f0 = xb[j*3+0] - xb[n*3+0]; f0 -= rintf(f0);
    float f1 = xb[j*3+1] - xb[n*3+1]; f1 -= rintf(f1);
    float f2 = xb[j*3+2] - xb[n*3+2]; f2 -= rintf(f2);
    const float* C = g_cell + b*9;
    float v0 = f0*C[0] + f1*C[3] + f2*C[6];
    float v1 = f0*C[1] + f1*C[4] + f2*C[7];
    float v2 = f0*C[2] + f1*C[5] + f2*C[8];
    float d  = sqrtf(v0*v0 + v1*v1 + v2*v2);
    g_vec[e*3+0] = v0; g_vec[e*3+1] = v1; g_vec[e*3+2] = v2;
    g_dist[e] = d;
    float inv = 1.f / (d + 1e-12f);
    g_u[e*3+0] = v0*inv; g_u[e*3+1] = v1*inv; g_u[e*3+2] = v2*inv;
}

// ---------------- triplet mask from INITIAL u (fixed thereafter) ----------------
__global__ void k_mask() {
    int node = blockIdx.x;
    __shared__ float su[KNN*3];
    int t = threadIdx.x;  // 64
    if (t < KNN*3) su[t] = g_u[node*KNN*3 + t];
    __syncthreads();
    for (int p = t; p < KNN*KNN; p += 64) {
        int jj = p / KNN, kk = p % KNN;
        const float* a = su + jj*3;
        const float* c = su + kk*3;
        float c0 = a[1]*c[2] - a[2]*c[1];
        float c1 = a[2]*c[0] - a[0]*c[2];
        float c2 = a[0]*c[1] - a[1]*c[0];
        g_mask[node*KNN*KNN + p] = (sqrtf(c0*c0 + c1*c1 + c2*c2) > 1e-3f) ? 1 : 0;
    }
}

// ---------------- first lin1 (per node): h = emb[z]; y = h @ W1[:128,:] + b1 ----------------
__global__ void __launch_bounds__(128) k_lin1n(
    const float* __restrict__ W1, const float* __restrict__ b1,
    const float* __restrict__ emb, const int* __restrict__ z)
{
    int node = blockIdx.x;
    int t = threadIdx.x;
    __shared__ float shh[FF];
    float hv = emb[z[node]*FF + t];
    g_h[node*FF + t] = hv;
    shh[t] = hv;
    __syncthreads();

    float acc = b1[t];
    #pragma unroll 4
    for (int f = 0; f < FF; f += 4) {
        float w0 = W1[(f+0)*FF + t];
        float w1 = W1[(f+1)*FF + t];
        float w2 = W1[(f+2)*FF + t];
        float w3 = W1[(f+3)*FF + t];
        float4 hv4 = *(const float4*)(shh + f);
        acc += hv4.x*w0 + hv4.y*w1 + hv4.z*w2 + hv4.w*w3;
    }
    g_y[node*FF + t] = acc;
}

// ---------------- fused MPNN layer (per node): aggr -> lin2 -> h += -> lin1(next) ----------
// Reads y from parity p, writes next-layer y to parity p^1 (cross-block race avoided).
// If awe != null, also emits per-node dots de = h·awe, dp = h·awp for the edge-weight kernel.
__global__ void __launch_bounds__(128) k_fusedL(
    const float* __restrict__ wl_row,   // W1 row 128 (dist weights) of current layer
    const float* __restrict__ W2, const float* __restrict__ b2,
    const float* __restrict__ W1n, const float* __restrict__ b1n,
    const float* __restrict__ awe, const float* __restrict__ awp, int p)
{
    int node = blockIdx.x;
    int b = node >> 8;
    int t = threadIdx.x;

    __shared__ float sdist[KNN];
    __shared__ int   sj[KNN];
    __shared__ float shm[FF];
    __shared__ float shh[FF];
    __shared__ float swe[4], swp[4];

    if (t < KNN) { sdist[t] = g_dist[node*KNN + t]; sj[t] = g_idx[node*KNN + t]; }
    __syncthreads();

    // aggr: msum = sum_k silu(y[j_k] + dist_k * wl)
    const float* yb = g_y + p*NNODE*FF + b*NAT*FF;
    float wl = wl_row[t];
    float s = 0.f;
    #pragma unroll 4
    for (int k = 0; k < KNN; k++) {
        float yv = yb[sj[k]*FF + t];
        s += siluf(yv + sdist[k]*wl);
    }
    shm[t] = s;
    __syncthreads();

    // lin2: h += silu(msum @ W2 + b2)
    float acc = b2[t];
    #pragma unroll 4
    for (int f = 0; f < FF; f += 4) {
        float w0 = W2[(f+0)*FF + t];
        float w1 = W2[(f+1)*FF + t];
        float w2 = W2[(f+2)*FF + t];
        float w3 = W2[(f+3)*FF + t];
        float4 mv = *(const float4*)(shm + f);
        acc += mv.x*w0 + mv.y*w1 + mv.z*w2 + mv.w*w3;
    }
    float hn = g_h[node*FF + t] + siluf(acc);
    g_h[node*FF + t] = hn;

    // per-node action dots (used by k_edgew: w_e = tanh(de_i + de_j))
    if (awe) {
        float re = hn * awe[t];
        float rp = hn * awp[t];
        #pragma unroll
        for (int o = 16; o; o >>= 1) {
            re += __shfl_xor_sync(0xffffffffu, re, o);
            rp += __shfl_xor_sync(0xffffffffu, rp, o);
        }
        if ((t & 31) == 0) { swe[t >> 5] = re; swp[t >> 5] = rp; }
        __syncthreads();
        if (t == 0) {
            g_de[node] = swe[0] + swe[1] + swe[2] + swe[3];
            g_dp[node] = swp[0] + swp[1] + swp[2] + swp[3];
        }
    }

    // lin1 of next layer (node-local h)
    if (W1n) {
        shh[t] = hn;
        __syncthreads();
        float a1 = b1n[t];
        #pragma unroll 4
        for (int f = 0; f < FF; f += 4) {
            float w0 = W1n[(f+0)*FF + t];
            float w1 = W1n[(f+1)*FF + t];
            float w2 = W1n[(f+2)*FF + t];
            float w3 = W1n[(f+3)*FF + t];
            float4 hv4 = *(const float4*)(shh + f);
            a1 += hv4.x*w0 + hv4.y*w1 + hv4.z*w2 + hv4.w*w3;
        }
        g_y[(p^1)*NNODE*FF + node*FF + t] = a1;
    }
}

// ---------------- edge weights (from precomputed dots) + strain/tri + x_cart ----------------
__global__ void __launch_bounds__(128) k_edgew()
{
    int node = blockIdx.x;
    int b = node >> 8;
    int t = threadIdx.x;
    int lane = t & 31;

    __shared__ float sh_we[KNN], sh_wp[KNN];
    __shared__ float su[KNN*3], sv[KNN*3];
    __shared__ float sT[6];

    if (t < KNN*3) { su[t] = g_u[node*KNN*3 + t]; sv[t] = g_vec[node*KNN*3 + t]; }
    if (t < KNN) {
        int j = g_idx[node*KNN + t];
        sh_we[t] = tanhf(g_de[node] + g_de[b*NAT + j]);
        sh_wp[t] = tanhf(g_dp[node] + g_dp[b*NAT + j]);
    }
    if (t < 6) sT[t] = 0.f;
    __syncthreads();

    // strain partial (symmetric 6) and x_cart
    if (t < 6) {
        int c = c_pc[t], d = c_pd[t];
        float s = 0.f;
        #pragma unroll
        for (int k = 0; k < KNN; k++) s += sh_we[k] * su[k*3+c] * su[k*3+d];
        atomicAdd(&g_strain[b*6 + t], s);
    } else if (t >= 16 && t < 19) {
        int c = t - 16;
        float s = 0.f;
        #pragma unroll
        for (int k = 0; k < KNN; k++) s += sh_wp[k] * sv[k*3+c];
        g_xcart[node*3 + c] = EPSC * s;
    }

    // tri partial over 576 pairs (cross products on the fly, symmetric 6)
    float T0=0.f,T1=0.f,T2=0.f,T3=0.f,T4=0.f,T5=0.f;
    const unsigned char* mp = g_mask + node*KNN*KNN;
    for (int p = t; p < KNN*KNN; p += 128) {
        if (!mp[p]) continue;
        int jj = p / KNN, kk = p - jj*KNN;
        float wjk = sh_we[jj] * sh_we[kk];
        const float* a = su + jj*3;
        const float* c = su + kk*3;
        float c0 = a[1]*c[2] - a[2]*c[1];
        float c1 = a[2]*c[0] - a[0]*c[2];
        float c2 = a[0]*c[1] - a[1]*c[0];
        T0 += wjk*c0*c0; T1 += wjk*c0*c1; T2 += wjk*c0*c2;
        T3 += wjk*c1*c1; T4 += wjk*c1*c2; T5 += wjk*c2*c2;
    }
    #pragma unroll
    for (int o = 16; o; o >>= 1) {
        T0 += __shfl_xor_sync(0xffffffffu, T0, o);
        T1 += __shfl_xor_sync(0xffffffffu, T1, o);
        T2 += __shfl_xor_sync(0xffffffffu, T2, o);
        T3 += __shfl_xor_sync(0xffffffffu, T3, o);
        T4 += __shfl_xor_sync(0xffffffffu, T4, o);
        T5 += __shfl_xor_sync(0xffffffffu, T5, o);
    }
    if (lane == 0) {
        atomicAdd(&sT[0], T0); atomicAdd(&sT[1], T1); atomicAdd(&sT[2], T2);
        atomicAdd(&sT[3], T3); atomicAdd(&sT[4], T4); atomicAdd(&sT[5], T5);
    }
    __syncthreads();
    if (t < 6) atomicAdd(&g_tri[b*6 + t], sT[t]);
}

// ---------------- per-batch action update; inv(old cell); zero accumulators ----------------
__global__ void k_action(int is_last, float* __restrict__ out) {
    int b = blockIdx.x;
    if (threadIdx.x != 0) return;
    float s6[6], t6[6];
    #pragma unroll
    for (int i = 0; i < 6; i++) {
        s6[i] = g_strain[b*6+i]; t6[i] = g_tri[b*6+i];
        g_strain[b*6+i] = 0.f;   g_tri[b*6+i] = 0.f;
    }
    const float NK  = (float)(NAT*KNN);
    const float NKK = (float)(NAT*KNN*KNN);
    float P[9];
    P[0] = s6[0]/NK + t6[0]/NKK;
    P[1] = s6[1]/NK + t6[1]/NKK; P[3] = P[1];
    P[2] = s6[2]/NK + t6[2]/NKK; P[6] = P[2];
    P[4] = s6[3]/NK + t6[3]/NKK;
    P[5] = s6[4]/NK + t6[4]/NKK; P[7] = P[5];
    P[8] = s6[5]/NK + t6[5]/NKK;
    float A[9];
    #pragma unroll
    for (int i = 0; i < 9; i++) A[i] = EPSC*P[i] + ((i % 4 == 0) ? 1.f : 0.f);
    float R[9], C[9], Rn[9];
    #pragma unroll
    for (int i = 0; i < 9; i++) { R[i] = g_rho[b*9+i]; C[i] = g_cell[b*9+i]; }
    #pragma unroll
    for (int i = 0; i < 3; i++)
        #pragma unroll
        for (int k = 0; k < 3; k++)
            Rn[i*3+k] = A[i*3+0]*R[0+k] + A[i*3+1]*R[3+k] + A[i*3+2]*R[6+k];
    // inverse of OLD geo_cell (adjugate)
    float det = C[0]*(C[4]*C[8]-C[5]*C[7]) - C[1]*(C[3]*C[8]-C[5]*C[6]) + C[2]*(C[3]*C[7]-C[4]*C[6]);
    float id = 1.f/det;
    float IV[9];
    IV[0]=(C[4]*C[8]-C[5]*C[7])*id;
    IV[1]=(C[2]*C[7]-C[1]*C[8])*id;
    IV[2]=(C[1]*C[5]-C[2]*C[4])*id;
    IV[3]=(C[5]*C[6]-C[3]*C[8])*id;
    IV[4]=(C[0]*C[8]-C[2]*C[6])*id;
    IV[5]=(C[2]*C[3]-C[0]*C[5])*id;
    IV[6]=(C[3]*C[7]-C[4]*C[6])*id;
    IV[7]=(C[1]*C[6]-C[0]*C[7])*id;
    IV[8]=(C[0]*C[4]-C[1]*C[3])*id;
    #pragma unroll
    for (int i = 0; i < 9; i++) {
        g_invcell[b*9+i] = IV[i];
        g_rho[b*9+i] = Rn[i];
        g_cell[b*9+i] = Rn[i];   // geo_cell = rho_prime (cell0 = I)
    }
    if (is_last) {
        #pragma unroll
        for (int i = 0; i < 9; i++) out[NNODE*3 + b*9 + i] = Rn[i];
    }
}

// ---------------- position update: x += x_cart @ inv(old cell); traj += x_cart ----------------
__global__ void k_pos(float* __restrict__ out) {
    int node = blockIdx.x * blockDim.x + threadIdx.x;
    if (node >= NNODE) return;
    int b = node >> 8;
    float xc0 = g_xcart[node*3+0];
    float xc1 = g_xcart[node*3+1];
    float xc2 = g_xcart[node*3+2];
    const float* iv = g_invcell + b*9;
    float xf0 = xc0*iv[0] + xc1*iv[3] + xc2*iv[6];
    float xf1 = xc0*iv[1] + xc1*iv[4] + xc2*iv[7];
    float xf2 = xc0*iv[2] + xc1*iv[5] + xc2*iv[8];
    g_x[node*3+0] += xf0;
    g_x[node*3+1] += xf1;
    g_x[node*3+2] += xf2;
    out[node*3+0] += xc0;
    out[node*3+1] += xc1;
    out[node*3+2] += xc2;
}

// ---------------- launch ----------------
extern "C" void kernel_launch(void* const* d_in, const int* in_sizes, int n_in,
                              void* d_out, int out_size) {
    const float* x_in = (const float*)d_in[1];
    const int*   z    = (const int*)  d_in[2];
    const float* emb  = (const float*)d_in[4];
    const float* mW1  = (const float*)d_in[5];
    const float* mb1  = (const float*)d_in[6];
    const float* mW2  = (const float*)d_in[7];
    const float* mb2  = (const float*)d_in[8];
    const float* uW1  = (const float*)d_in[9];
    const float* ub1  = (const float*)d_in[10];
    const float* uW2  = (const float*)d_in[11];
    const float* ub2  = (const float*)d_in[12];
    const float* awe  = (const float*)d_in[13];
    const float* awp  = (const float*)d_in[14];
    float* out = (float*)d_out;

    const int SZ1 = (FF+1)*FF;

    k_init <<<48, 256>>>(x_in, out);
    k_knn  <<<NNODE, 256>>>();
    k_edges<<<(NEDGE + 255)/256, 256>>>();
    k_mask <<<NNODE, 64>>>();

    k_lin1n<<<NNODE, 128>>>(mW1, mb1, emb, z);
    int p = 0;
    for (int l = 0; l < LL; l++) {
        const float* W1n = (l < 3) ? (mW1 + (l+1)*SZ1) : uW1;
        const float* b1n = (l < 3) ? (mb1 + (l+1)*FF)  : ub1;
        k_fusedL<<<NNODE, 128>>>(mW1 + l*SZ1 + FF*FF, mW2 + l*FF*FF, mb2 + l*FF,
                                 W1n, b1n, (const float*)0, (const float*)0, p);
        p ^= 1;
    }
    for (int l = 0; l < LL; l++) {
        const float* W1n = (l < 3) ? (uW1 + (l+1)*SZ1) : (const float*)0;
        const float* b1n = (l < 3) ? (ub1 + (l+1)*FF)  : (const float*)0;
        k_fusedL<<<NNODE, 128>>>(uW1 + l*SZ1 + FF*FF, uW2 + l*FF*FF, ub2 + l*FF,
                                 W1n, b1n, awe + l*FF, awp + l*FF, p);
        p ^= 1;
        k_edgew<<<NNODE, 128>>>();
        k_action<<<BB, 32>>>(l == LL-1 ? 1 : 0, out);
        k_pos  <<<(NNODE + 255)/256, 256>>>(out);
        if (l < LL-1) k_edges<<<(NEDGE + 255)/256, 256>>>();
    }
}

// round 12
// speedup vs baseline: 1.1783x; 1.0331x over previous
#include <cuda_runtime.h>
#include <math.h>

#define BB 16
#define NAT 256
#define KNN 24
#define FF 128
#define LL 4
#define EPSC 0.01f
#define NNODE (BB*NAT)
#define NEDGE (NNODE*KNN)
#define NPAIR ((KNN*(KNN-1))/2)   // 276 pairs j<k

// ---------------- scratch (device globals; no allocation allowed) ----------------
__device__ float g_x[NNODE*3];
__device__ int   g_idx[NEDGE];
__device__ float g_h[NNODE*FF];
__device__ float g_y[2*NNODE*FF];    // ping-pong per-node W1 transform
__device__ float g_de[NNODE];        // per-node dot(h, act_we)
__device__ float g_dp[NNODE];        // per-node dot(h, actpos_we)
__device__ float g_vec[NEDGE*3];
__device__ float g_dist[NEDGE];
__device__ float g_u[NEDGE*3];
__device__ unsigned char g_mask[NNODE*KNN*KNN];
__device__ uchar2 g_pairs[NPAIR];    // (j,k) with j<k
__device__ float g_xcart[NNODE*3];
__device__ float g_strain[BB*6];   // symmetric 3x3 packed: 00,01,02,11,12,22
__device__ float g_tri[BB*6];
__device__ float g_cell[BB*9];     // geo_cell (row-major)
__device__ float g_rho[BB*9];      // action_rho
__device__ float g_invcell[BB*9];

__constant__ int c_pc[6] = {0,0,0,1,1,2};
__constant__ int c_pd[6] = {0,1,2,1,2,2};

__device__ __forceinline__ float siluf(float a) {
    return a / (1.f + expf(-a));
}

// ---------------- init: x = mod(x,1), cells = I, accumulators = 0, traj = 0, pair LUT ------
__global__ void k_init(const float* __restrict__ x_in, float* __restrict__ out) {
    int i = blockIdx.x * blockDim.x + threadIdx.x;
    if (i < NNODE*3) { float v = x_in[i]; g_x[i] = v - floorf(v); out[i] = 0.f; }
    if (i < BB*9) {
        float id = ((i % 9) % 4 == 0) ? 1.f : 0.f;
        g_cell[i] = id; g_rho[i] = id;
    }
    if (i < BB*6) { g_strain[i] = 0.f; g_tri[i] = 0.f; }
    if (i < NPAIR) {
        int r = i, jj = 0;
        while (r >= KNN-1-jj) { r -= KNN-1-jj; jj++; }
        g_pairs[i] = make_uchar2((unsigned char)jj, (unsigned char)(jj+1+r));
    }
}

// ---------------- kNN (periodic min-image, cell = I), exact top_k tie-break ----------------
// rank via u64 keys: key = (float_bits(d) << 32) | j ; d >= 0 so bits are order-monotone,
// and low bits give the (d equal, j < t) tie-break exactly.
__global__ void k_knn() {
    int b = blockIdx.x >> 8;
    int i = blockIdx.x & 255;
    __shared__ float sx[NAT*3];
    __shared__ __align__(16) unsigned long long skey[NAT];
    int t = threadIdx.x;
    for (int q = t; q < NAT*3; q += 256) sx[q] = g_x[b*NAT*3 + q];
    __syncthreads();
    float xi0 = sx[i*3+0], xi1 = sx[i*3+1], xi2 = sx[i*3+2];
    float d0 = sx[t*3+0] - xi0; d0 -= rintf(d0);
    float d1 = sx[t*3+1] - xi1; d1 -= rintf(d1);
    float d2 = sx[t*3+2] - xi2; d2 -= rintf(d2);
    float d = sqrtf(d0*d0 + d1*d1 + d2*d2);
    if (t == i) d += 1e6f;
    unsigned long long kt = ((unsigned long long)__float_as_uint(d) << 32) | (unsigned)t;
    skey[t] = kt;
    __syncthreads();
    int rank = 0;
    const ulonglong2* s2 = (const ulonglong2*)skey;
    #pragma unroll 8
    for (int q = 0; q < NAT/2; q++) {
        ulonglong2 v = s2[q];
        rank += (v.x < kt);
        rank += (v.y < kt);
    }
    if (rank < KNN) g_idx[(b*NAT + i)*KNN + rank] = t;
}

// ---------------- initial edge vectors: vec = (frac - round(frac)) @ cell ----------------
__global__ void k_edges() {
    int e = blockIdx.x * blockDim.x + threadIdx.x;
    if (e >= NEDGE) return;
    int b = e / (NAT*KNN);
    int n = (e / KNN) & 255;
    int j = g_idx[e];
    const float* xb = g_x + b*NAT*3;
    float f0 = xb[j*3+0] - xb[n*3+0]; f0 -= rintf(f0);
    float f1 = xb[j*3+1] - xb[n*3+1]; f1 -= rintf(f1);
    float f2 = xb[j*3+2] - xb[n*3+2]; f2 -= rintf(f2);
    const float* C = g_cell + b*9;
    float v0 = f0*C[0] + f1*C[3] + f2*C[6];
    float v1 = f0*C[1] + f1*C[4] + f2*C[7];
    float v2 = f0*C[2] + f1*C[5] + f2*C[8];
    float d  = sqrtf(v0*v0 + v1*v1 + v2*v2);
    g_vec[e*3+0] = v0; g_vec[e*3+1] = v1; g_vec[e*3+2] = v2;
    g_dist[e] = d;
    float inv = 1.f / (d + 1e-12f);
    g_u[e*3+0] = v0*inv; g_u[e*3+1] = v1*inv; g_u[e*3+2] = v2*inv;
}

// ---------------- triplet mask from INITIAL u (fixed thereafter) ----------------
__global__ void k_mask() {
    int node = blockIdx.x;
    __shared__ float su[KNN*3];
    int t = threadIdx.x;  // 64
    if (t < KNN*3) su[t] = g_u[node*KNN*3 + t];
    __syncthreads();
    for (int p = t; p < KNN*KNN; p += 64) {
        int jj = p / KNN, kk = p % KNN;
        const float* a = su + jj*3;
        const float* c = su + kk*3;
        float c0 = a[1]*c[2] - a[2]*c[1];
        float c1 = a[2]*c[0] - a[0]*c[2];
        float c2 = a[0]*c[1] - a[1]*c[0];
        g_mask[node*KNN*KNN + p] = (sqrtf(c0*c0 + c1*c1 + c2*c2) > 1e-3f) ? 1 : 0;
    }
}

// ---------------- first lin1 (per node): h = emb[z]; y = h @ W1[:128,:] + b1 ----------------
__global__ void __launch_bounds__(128) k_lin1n(
    const float* __restrict__ W1, const float* __restrict__ b1,
    const float* __restrict__ emb, const int* __restrict__ z)
{
    int node = blockIdx.x;
    int t = threadIdx.x;
    __shared__ float shh[FF];
    float hv = emb[z[node]*FF + t];
    g_h[node*FF + t] = hv;
    shh[t] = hv;
    __syncthreads();

    float acc = b1[t];
    #pragma unroll 4
    for (int f = 0; f < FF; f += 4) {
        float w0 = W1[(f+0)*FF + t];
        float w1 = W1[(f+1)*FF + t];
        float w2 = W1[(f+2)*FF + t];
        float w3 = W1[(f+3)*FF + t];
        float4 hv4 = *(const float4*)(shh + f);
        acc += hv4.x*w0 + hv4.y*w1 + hv4.z*w2 + hv4.w*w3;
    }
    g_y[node*FF + t] = acc;
}

// ---------------- fused MPNN layer (per node): aggr -> lin2 -> h += -> lin1(next) ----------
// Reads y from parity p, writes next-layer y to parity p^1 (cross-block race avoided).
// If awe != null, also emits per-node dots de = h·awe, dp = h·awp for the edge-weight kernel.
__global__ void __launch_bounds__(128) k_fusedL(
    const float* __restrict__ wl_row,   // W1 row 128 (dist weights) of current layer
    const float* __restrict__ W2, const float* __restrict__ b2,
    const float* __restrict__ W1n, const float* __restrict__ b1n,
    const float* __restrict__ awe, const float* __restrict__ awp, int p)
{
    int node = blockIdx.x;
    int b = node >> 8;
    int t = threadIdx.x;

    __shared__ float sdist[KNN];
    __shared__ int   sj[KNN];
    __shared__ float shm[FF];
    __shared__ float shh[FF];
    __shared__ float swe[4], swp[4];

    if (t < KNN) { sdist[t] = g_dist[node*KNN + t]; sj[t] = g_idx[node*KNN + t]; }
    __syncthreads();

    // aggr: msum = sum_k silu(y[j_k] + dist_k * wl)
    const float* yb = g_y + p*NNODE*FF + b*NAT*FF;
    float wl = wl_row[t];
    float s = 0.f;
    #pragma unroll 4
    for (int k = 0; k < KNN; k++) {
        float yv = yb[sj[k]*FF + t];
        s += siluf(yv + sdist[k]*wl);
    }
    shm[t] = s;
    __syncthreads();

    // lin2: h += silu(msum @ W2 + b2)
    float acc = b2[t];
    #pragma unroll 4
    for (int f = 0; f < FF; f += 4) {
        float w0 = W2[(f+0)*FF + t];
        float w1 = W2[(f+1)*FF + t];
        float w2 = W2[(f+2)*FF + t];
        float w3 = W2[(f+3)*FF + t];
        float4 mv = *(const float4*)(shm + f);
        acc += mv.x*w0 + mv.y*w1 + mv.z*w2 + mv.w*w3;
    }
    float hn = g_h[node*FF + t] + siluf(acc);
    g_h[node*FF + t] = hn;

    // per-node action dots (used by k_edgew: w_e = tanh(de_i + de_j))
    if (awe) {
        float re = hn * awe[t];
        float rp = hn * awp[t];
        #pragma unroll
        for (int o = 16; o; o >>= 1) {
            re += __shfl_xor_sync(0xffffffffu, re, o);
            rp += __shfl_xor_sync(0xffffffffu, rp, o);
        }
        if ((t & 31) == 0) { swe[t >> 5] = re; swp[t >> 5] = rp; }
        __syncthreads();
        if (t == 0) {
            g_de[node] = swe[0] + swe[1] + swe[2] + swe[3];
            g_dp[node] = swp[0] + swp[1] + swp[2] + swp[3];
        }
    }

    // lin1 of next layer (node-local h)
    if (W1n) {
        shh[t] = hn;
        __syncthreads();
        float a1 = b1n[t];
        #pragma unroll 4
        for (int f = 0; f < FF; f += 4) {
            float w0 = W1n[(f+0)*FF + t];
            float w1 = W1n[(f+1)*FF + t];
            float w2 = W1n[(f+2)*FF + t];
            float w3 = W1n[(f+3)*FF + t];
            float4 hv4 = *(const float4*)(shh + f);
            a1 += hv4.x*w0 + hv4.y*w1 + hv4.z*w2 + hv4.w*w3;
        }
        g_y[(p^1)*NNODE*FF + node*FF + t] = a1;
    }
}

// ---------------- edge weights (from precomputed dots) + strain/tri + x_cart ----------------
__global__ void __launch_bounds__(128) k_edgew()
{
    int node = blockIdx.x;
    int b = node >> 8;
    int t = threadIdx.x;
    int lane = t & 31;

    __shared__ float sh_we[KNN], sh_wp[KNN];
    __shared__ float su[KNN*3], sv[KNN*3];
    __shared__ float sT[6];

    if (t < KNN*3) { su[t] = g_u[node*KNN*3 + t]; sv[t] = g_vec[node*KNN*3 + t]; }
    if (t < KNN) {
        int j = g_idx[node*KNN + t];
        sh_we[t] = tanhf(g_de[node] + g_de[b*NAT + j]);
        sh_wp[t] = tanhf(g_dp[node] + g_dp[b*NAT + j]);
    }
    if (t < 6) sT[t] = 0.f;
    __syncthreads();

    // strain partial (symmetric 6) and x_cart
    if (t < 6) {
        int c = c_pc[t], d = c_pd[t];
        float s = 0.f;
        #pragma unroll
        for (int k = 0; k < KNN; k++) s += sh_we[k] * su[k*3+c] * su[k*3+d];
        atomicAdd(&g_strain[b*6 + t], s);
    } else if (t >= 16 && t < 19) {
        int c = t - 16;
        float s = 0.f;
        #pragma unroll
        for (int k = 0; k < KNN; k++) s += sh_wp[k] * sv[k*3+c];
        g_xcart[node*3 + c] = EPSC * s;
    }

    // tri partial: symmetric in (j,k), diagonal always masked -> 2 * sum over j<k (276 pairs)
    float T0=0.f,T1=0.f,T2=0.f,T3=0.f,T4=0.f,T5=0.f;
    const unsigned char* mp = g_mask + node*KNN*KNN;
    for (int q = t; q < NPAIR; q += 128) {
        uchar2 pr = g_pairs[q];
        int jj = pr.x, kk = pr.y;
        if (!mp[jj*KNN + kk]) continue;
        float wjk = sh_we[jj] * sh_we[kk];
        const float* a = su + jj*3;
        const float* c = su + kk*3;
        float c0 = a[1]*c[2] - a[2]*c[1];
        float c1 = a[2]*c[0] - a[0]*c[2];
        float c2 = a[0]*c[1] - a[1]*c[0];
        T0 += wjk*c0*c0; T1 += wjk*c0*c1; T2 += wjk*c0*c2;
        T3 += wjk*c1*c1; T4 += wjk*c1*c2; T5 += wjk*c2*c2;
    }
    #pragma unroll
    for (int o = 16; o; o >>= 1) {
        T0 += __shfl_xor_sync(0xffffffffu, T0, o);
        T1 += __shfl_xor_sync(0xffffffffu, T1, o);
        T2 += __shfl_xor_sync(0xffffffffu, T2, o);
        T3 += __shfl_xor_sync(0xffffffffu, T3, o);
        T4 += __shfl_xor_sync(0xffffffffu, T4, o);
        T5 += __shfl_xor_sync(0xffffffffu, T5, o);
    }
    if (lane == 0) {
        atomicAdd(&sT[0], 2.f*T0); atomicAdd(&sT[1], 2.f*T1); atomicAdd(&sT[2], 2.f*T2);
        atomicAdd(&sT[3], 2.f*T3); atomicAdd(&sT[4], 2.f*T4); atomicAdd(&sT[5], 2.f*T5);
    }
    __syncthreads();
    if (t < 6) atomicAdd(&g_tri[b*6 + t], sT[t]);
}

// ---------------- per-batch action update; inv(old cell); zero accumulators ----------------
__global__ void k_action(int is_last, float* __restrict__ out) {
    int b = blockIdx.x;
    if (threadIdx.x != 0) return;
    float s6[6], t6[6];
    #pragma unroll
    for (int i = 0; i < 6; i++) {
        s6[i] = g_strain[b*6+i]; t6[i] = g_tri[b*6+i];
        g_strain[b*6+i] = 0.f;   g_tri[b*6+i] = 0.f;
    }
    const float NK  = (float)(NAT*KNN);
    const float NKK = (float)(NAT*KNN*KNN);
    float P[9];
    P[0] = s6[0]/NK + t6[0]/NKK;
    P[1] = s6[1]/NK + t6[1]/NKK; P[3] = P[1];
    P[2] = s6[2]/NK + t6[2]/NKK; P[6] = P[2];
    P[4] = s6[3]/NK + t6[3]/NKK;
    P[5] = s6[4]/NK + t6[4]/NKK; P[7] = P[5];
    P[8] = s6[5]/NK + t6[5]/NKK;
    float A[9];
    #pragma unroll
    for (int i = 0; i < 9; i++) A[i] = EPSC*P[i] + ((i % 4 == 0) ? 1.f : 0.f);
    float R[9], C[9], Rn[9];
    #pragma unroll
    for (int i = 0; i < 9; i++) { R[i] = g_rho[b*9+i]; C[i] = g_cell[b*9+i]; }
    #pragma unroll
    for (int i = 0; i < 3; i++)
        #pragma unroll
        for (int k = 0; k < 3; k++)
            Rn[i*3+k] = A[i*3+0]*R[0+k] + A[i*3+1]*R[3+k] + A[i*3+2]*R[6+k];
    // inverse of OLD geo_cell (adjugate)
    float det = C[0]*(C[4]*C[8]-C[5]*C[7]) - C[1]*(C[3]*C[8]-C[5]*C[6]) + C[2]*(C[3]*C[7]-C[4]*C[6]);
    float id = 1.f/det;
    float IV[9];
    IV[0]=(C[4]*C[8]-C[5]*C[7])*id;
    IV[1]=(C[2]*C[7]-C[1]*C[8])*id;
    IV[2]=(C[1]*C[5]-C[2]*C[4])*id;
    IV[3]=(C[5]*C[6]-C[3]*C[8])*id;
    IV[4]=(C[0]*C[8]-C[2]*C[6])*id;
    IV[5]=(C[2]*C[3]-C[0]*C[5])*id;
    IV[6]=(C[3]*C[7]-C[4]*C[6])*id;
    IV[7]=(C[1]*C[6]-C[0]*C[7])*id;
    IV[8]=(C[0]*C[4]-C[1]*C[3])*id;
    #pragma unroll
    for (int i = 0; i < 9; i++) {
        g_invcell[b*9+i] = IV[i];
        g_rho[b*9+i] = Rn[i];
        g_cell[b*9+i] = Rn[i];   // geo_cell = rho_prime (cell0 = I)
    }
    if (is_last) {
        #pragma unroll
        for (int i = 0; i < 9; i++) out[NNODE*3 + b*9 + i] = Rn[i];
    }
}

// ---------------- position update: x += x_cart @ inv(old cell); traj += x_cart ----------------
__global__ void k_pos(float* __restrict__ out) {
    int node = blockIdx.x * blockDim.x + threadIdx.x;
    if (node >= NNODE) return;
    int b = node >> 8;
    float xc0 = g_xcart[node*3+0];
    float xc1 = g_xcart[node*3+1];
    float xc2 = g_xcart[node*3+2];
    const float* iv = g_invcell + b*9;
    float xf0 = xc0*iv[0] + xc1*iv[3] + xc2*iv[6];
    float xf1 = xc0*iv[1] + xc1*iv[4] + xc2*iv[7];
    float xf2 = xc0*iv[2] + xc1*iv[5] + xc2*iv[8];
    g_x[node*3+0] += xf0;
    g_x[node*3+1] += xf1;
    g_x[node*3+2] += xf2;
    out[node*3+0] += xc0;
    out[node*3+1] += xc1;
    out[node*3+2] += xc2;
}

// ---------------- launch ----------------
extern "C" void kernel_launch(void* const* d_in, const int* in_sizes, int n_in,
                              void* d_out, int out_size) {
    const float* x_in = (const float*)d_in[1];
    const int*   z    = (const int*)  d_in[2];
    const float* emb  = (const float*)d_in[4];
    const float* mW1  = (const float*)d_in[5];
    const float* mb1  = (const float*)d_in[6];
    const float* mW2  = (const float*)d_in[7];
    const float* mb2  = (const float*)d_in[8];
    const float* uW1  = (const float*)d_in[9];
    const float* ub1  = (const float*)d_in[10];
    const float* uW2  = (const float*)d_in[11];
    const float* ub2  = (const float*)d_in[12];
    const float* awe  = (const float*)d_in[13];
    const float* awp  = (const float*)d_in[14];
    float* out = (float*)d_out;

    const int SZ1 = (FF+1)*FF;

    k_init <<<48, 256>>>(x_in, out);
    k_knn  <<<NNODE, 256>>>();
    k_edges<<<(NEDGE + 255)/256, 256>>>();
    k_mask <<<NNODE, 64>>>();

    k_lin1n<<<NNODE, 128>>>(mW1, mb1, emb, z);
    int p = 0;
    for (int l = 0; l < LL; l++) {
        const float* W1n = (l < 3) ? (mW1 + (l+1)*SZ1) : uW1;
        const float* b1n = (l < 3) ? (mb1 + (l+1)*FF)  : ub1;
        k_fusedL<<<NNODE, 128>>>(mW1 + l*SZ1 + FF*FF, mW2 + l*FF*FF, mb2 + l*FF,
                                 W1n, b1n, (const float*)0, (const float*)0, p);
        p ^= 1;
    }
    for (int l = 0; l < LL; l++) {
        const float* W1n = (l < 3) ? (uW1 + (l+1)*SZ1) : (const float*)0;
        const float* b1n = (l < 3) ? (ub1 + (l+1)*FF)  : (const float*)0;
        k_fusedL<<<NNODE, 128>>>(uW1 + l*SZ1 + FF*FF, uW2 + l*FF*FF, ub2 + l*FF,
                                 W1n, b1n, awe + l*FF, awp + l*FF, p);
        p ^= 1;
        k_edgew<<<NNODE, 128>>>();
        k_action<<<BB, 32>>>(l == LL-1 ? 1 : 0, out);
        k_pos  <<<(NNODE + 255)/256, 256>>>(out);
        if (l < LL-1) k_edges<<<(NEDGE + 255)/256, 256>>>();
    }
}

// round 13
// speedup vs baseline: 1.2454x; 1.0569x over previous
#include <cuda_runtime.h>
#include <math.h>

#define BB 16
#define NAT 256
#define KNN 24
#define FF 128
#define LL 4
#define EPSC 0.01f
#define NNODE (BB*NAT)
#define NEDGE (NNODE*KNN)
#define NPAIR ((KNN*(KNN-1))/2)   // 276 pairs j<k

// ---------------- scratch (device globals; no allocation allowed) ----------------
__device__ float g_x[NNODE*3];
__device__ int   g_idx[NEDGE];
__device__ float g_h[NNODE*FF];
__device__ float g_y[2*NNODE*FF];    // ping-pong per-node W1 transform
__device__ float g_de[NNODE];        // per-node dot(h, act_we)
__device__ float g_dp[NNODE];        // per-node dot(h, actpos_we)
__device__ float g_vec[NEDGE*3];
__device__ float g_dist[NEDGE];
__device__ float g_u[NEDGE*3];
__device__ unsigned char g_mask[NNODE*KNN*KNN];
__device__ uchar2 g_pairs[NPAIR];    // (j,k) with j<k
__device__ float g_xcart[NNODE*3];
__device__ float g_strain[BB*6];   // symmetric 3x3 packed: 00,01,02,11,12,22
__device__ float g_tri[BB*6];
__device__ float g_cell[BB*9];     // geo_cell (row-major)
__device__ float g_rho[BB*9];      // action_rho
__device__ float g_invcell[BB*9];

__constant__ int c_pc[6] = {0,0,0,1,1,2};
__constant__ int c_pd[6] = {0,1,2,1,2,2};

__device__ __forceinline__ float siluf(float a) {
    return a / (1.f + expf(-a));
}

// 128x128 GEMM microkernel: out[t] = sum_f sin[f] * W[f*FF + t]
// Warp w handles f in [32w, 32w+32); lane loads float4 of 4 output columns (LDG.128).
// 4 f-chunk partials combined in chunk order via shared 'red' (512 floats).
// Internally syncs: opening sync makes 'sin' visible and 'red' free; closing sync before read.
__device__ __forceinline__ float gemm128(
    const float* __restrict__ W, const float* sin, float* red, int t)
{
    int lane = t & 31, w = t >> 5;
    __syncthreads();
    float4 a = make_float4(0.f, 0.f, 0.f, 0.f);
    #pragma unroll 8
    for (int f = 0; f < 32; f++) {
        float hv = sin[32*w + f];
        float4 wv = ((const float4*)(W + (32*w + f)*FF))[lane];
        a.x += hv*wv.x; a.y += hv*wv.y; a.z += hv*wv.z; a.w += hv*wv.w;
    }
    ((float4*)(red + w*FF))[lane] = a;
    __syncthreads();
    return red[0*FF + t] + red[1*FF + t] + red[2*FF + t] + red[3*FF + t];
}

// ---------------- init: x = mod(x,1), cells = I, accumulators = 0, traj = 0, pair LUT ------
__global__ void k_init(const float* __restrict__ x_in, float* __restrict__ out) {
    int i = blockIdx.x * blockDim.x + threadIdx.x;
    if (i < NNODE*3) { float v = x_in[i]; g_x[i] = v - floorf(v); out[i] = 0.f; }
    if (i < BB*9) {
        float id = ((i % 9) % 4 == 0) ? 1.f : 0.f;
        g_cell[i] = id; g_rho[i] = id;
    }
    if (i < BB*6) { g_strain[i] = 0.f; g_tri[i] = 0.f; }
    if (i < NPAIR) {
        int r = i, jj = 0;
        while (r >= KNN-1-jj) { r -= KNN-1-jj; jj++; }
        g_pairs[i] = make_uchar2((unsigned char)jj, (unsigned char)(jj+1+r));
    }
}

// ---------------- kNN (periodic min-image, cell = I), exact top_k tie-break ----------------
__global__ void k_knn() {
    int b = blockIdx.x >> 8;
    int i = blockIdx.x & 255;
    __shared__ float sx[NAT*3];
    __shared__ __align__(16) unsigned long long skey[NAT];
    int t = threadIdx.x;
    for (int q = t; q < NAT*3; q += 256) sx[q] = g_x[b*NAT*3 + q];
    __syncthreads();
    float xi0 = sx[i*3+0], xi1 = sx[i*3+1], xi2 = sx[i*3+2];
    float d0 = sx[t*3+0] - xi0; d0 -= rintf(d0);
    float d1 = sx[t*3+1] - xi1; d1 -= rintf(d1);
    float d2 = sx[t*3+2] - xi2; d2 -= rintf(d2);
    float d = sqrtf(d0*d0 + d1*d1 + d2*d2);
    if (t == i) d += 1e6f;
    unsigned long long kt = ((unsigned long long)__float_as_uint(d) << 32) | (unsigned)t;
    skey[t] = kt;
    __syncthreads();
    int rank = 0;
    const ulonglong2* s2 = (const ulonglong2*)skey;
    #pragma unroll 8
    for (int q = 0; q < NAT/2; q++) {
        ulonglong2 v = s2[q];
        rank += (v.x < kt);
        rank += (v.y < kt);
    }
    if (rank < KNN) g_idx[(b*NAT + i)*KNN + rank] = t;
}

// ---------------- initial edge vectors: vec = (frac - round(frac)) @ cell ----------------
__global__ void k_edges() {
    int e = blockIdx.x * blockDim.x + threadIdx.x;
    if (e >= NEDGE) return;
    int b = e / (NAT*KNN);
    int n = (e / KNN) & 255;
    int j = g_idx[e];
    const float* xb = g_x + b*NAT*3;
    float f0 = xb[j*3+0] - xb[n*3+0]; f0 -= rintf(f0);
    float f1 = xb[j*3+1] - xb[n*3+1]; f1 -= rintf(f1);
    float f2 = xb[j*3+2] - xb[n*3+2]; f2 -= rintf(f2);
    const float* C = g_cell + b*9;
    float v0 = f0*C[0] + f1*C[3] + f2*C[6];
    float v1 = f0*C[1] + f1*C[4] + f2*C[7];
    float v2 = f0*C[2] + f1*C[5] + f2*C[8];
    float d  = sqrtf(v0*v0 + v1*v1 + v2*v2);
    g_vec[e*3+0] = v0; g_vec[e*3+1] = v1; g_vec[e*3+2] = v2;
    g_dist[e] = d;
    float inv = 1.f / (d + 1e-12f);
    g_u[e*3+0] = v0*inv; g_u[e*3+1] = v1*inv; g_u[e*3+2] = v2*inv;
}

// ---------------- triplet mask from INITIAL u (fixed thereafter) ----------------
__global__ void k_mask() {
    int node = blockIdx.x;
    __shared__ float su[KNN*3];
    int t = threadIdx.x;  // 64
    if (t < KNN*3) su[t] = g_u[node*KNN*3 + t];
    __syncthreads();
    for (int p = t; p < KNN*KNN; p += 64) {
        int jj = p / KNN, kk = p % KNN;
        const float* a = su + jj*3;
        const float* c = su + kk*3;
        float c0 = a[1]*c[2] - a[2]*c[1];
        float c1 = a[2]*c[0] - a[0]*c[2];
        float c2 = a[0]*c[1] - a[1]*c[0];
        g_mask[node*KNN*KNN + p] = (sqrtf(c0*c0 + c1*c1 + c2*c2) > 1e-3f) ? 1 : 0;
    }
}

// ---------------- first lin1 (per node): h = emb[z]; y = h @ W1[:128,:] + b1 ----------------
__global__ void __launch_bounds__(128) k_lin1n(
    const float* __restrict__ W1, const float* __restrict__ b1,
    const float* __restrict__ emb, const int* __restrict__ z)
{
    int node = blockIdx.x;
    int t = threadIdx.x;
    __shared__ float shh[FF];
    __shared__ float red[4*FF];
    float hv = emb[z[node]*FF + t];
    g_h[node*FF + t] = hv;
    shh[t] = hv;
    float acc = gemm128(W1, shh, red, t) + b1[t];
    g_y[node*FF + t] = acc;
}

// ---------------- fused MPNN layer (per node): aggr -> lin2 -> h += -> lin1(next) ----------
// Reads y from parity p, writes next-layer y to parity p^1 (cross-block race avoided).
// If awe != null, also emits per-node dots de = h·awe, dp = h·awp for the edge-weight kernel.
__global__ void __launch_bounds__(128) k_fusedL(
    const float* __restrict__ wl_row,   // W1 row 128 (dist weights) of current layer
    const float* __restrict__ W2, const float* __restrict__ b2,
    const float* __restrict__ W1n, const float* __restrict__ b1n,
    const float* __restrict__ awe, const float* __restrict__ awp, int p)
{
    int node = blockIdx.x;
    int b = node >> 8;
    int t = threadIdx.x;

    __shared__ float sdist[KNN];
    __shared__ int   sj[KNN];
    __shared__ float shm[FF];
    __shared__ float shh[FF];
    __shared__ float red[4*FF];
    __shared__ float swe[4], swp[4];

    if (t < KNN) { sdist[t] = g_dist[node*KNN + t]; sj[t] = g_idx[node*KNN + t]; }
    __syncthreads();

    // aggr: msum = sum_k silu(y[j_k] + dist_k * wl)
    const float* yb = g_y + p*NNODE*FF + b*NAT*FF;
    float wl = wl_row[t];
    float s = 0.f;
    #pragma unroll 4
    for (int k = 0; k < KNN; k++) {
        float yv = yb[sj[k]*FF + t];
        s += siluf(yv + sdist[k]*wl);
    }
    shm[t] = s;

    // lin2: h += silu(msum @ W2 + b2)   (gemm128 syncs internally)
    float acc = gemm128(W2, shm, red, t) + b2[t];
    float hn = g_h[node*FF + t] + siluf(acc);
    g_h[node*FF + t] = hn;
    shh[t] = hn;

    // per-node action dots (used by k_edgew: w_e = tanh(de_i + de_j))
    if (awe) {
        float re = hn * awe[t];
        float rp = hn * awp[t];
        #pragma unroll
        for (int o = 16; o; o >>= 1) {
            re += __shfl_xor_sync(0xffffffffu, re, o);
            rp += __shfl_xor_sync(0xffffffffu, rp, o);
        }
        if ((t & 31) == 0) { swe[t >> 5] = re; swp[t >> 5] = rp; }
        __syncthreads();
        if (t == 0) {
            g_de[node] = swe[0] + swe[1] + swe[2] + swe[3];
            g_dp[node] = swp[0] + swp[1] + swp[2] + swp[3];
        }
    }

    // lin1 of next layer (node-local h; gemm128 opening sync protects shh and red)
    if (W1n) {
        float a1 = gemm128(W1n, shh, red, t) + b1n[t];
        g_y[(p^1)*NNODE*FF + node*FF + t] = a1;
    }
}

// ---------------- edge weights (from precomputed dots) + strain/tri + x_cart ----------------
__global__ void __launch_bounds__(128) k_edgew()
{
    int node = blockIdx.x;
    int b = node >> 8;
    int t = threadIdx.x;
    int lane = t & 31;

    __shared__ float sh_we[KNN], sh_wp[KNN];
    __shared__ float su[KNN*3], sv[KNN*3];
    __shared__ float sT[6];

    if (t < KNN*3) { su[t] = g_u[node*KNN*3 + t]; sv[t] = g_vec[node*KNN*3 + t]; }
    if (t < KNN) {
        int j = g_idx[node*KNN + t];
        sh_we[t] = tanhf(g_de[node] + g_de[b*NAT + j]);
        sh_wp[t] = tanhf(g_dp[node] + g_dp[b*NAT + j]);
    }
    if (t < 6) sT[t] = 0.f;
    __syncthreads();

    // strain partial (symmetric 6) and x_cart
    if (t < 6) {
        int c = c_pc[t], d = c_pd[t];
        float s = 0.f;
        #pragma unroll
        for (int k = 0; k < KNN; k++) s += sh_we[k] * su[k*3+c] * su[k*3+d];
        atomicAdd(&g_strain[b*6 + t], s);
    } else if (t >= 16 && t < 19) {
        int c = t - 16;
        float s = 0.f;
        #pragma unroll
        for (int k = 0; k < KNN; k++) s += sh_wp[k] * sv[k*3+c];
        g_xcart[node*3 + c] = EPSC * s;
    }

    // tri partial: symmetric in (j,k), diagonal always masked -> 2 * sum over j<k (276 pairs)
    float T0=0.f,T1=0.f,T2=0.f,T3=0.f,T4=0.f,T5=0.f;
    const unsigned char* mp = g_mask + node*KNN*KNN;
    for (int q = t; q < NPAIR; q += 128) {
        uchar2 pr = g_pairs[q];
        int jj = pr.x, kk = pr.y;
        if (!mp[jj*KNN + kk]) continue;
        float wjk = sh_we[jj] * sh_we[kk];
        const float* a = su + jj*3;
        const float* c = su + kk*3;
        float c0 = a[1]*c[2] - a[2]*c[1];
        float c1 = a[2]*c[0] - a[0]*c[2];
        float c2 = a[0]*c[1] - a[1]*c[0];
        T0 += wjk*c0*c0; T1 += wjk*c0*c1; T2 += wjk*c0*c2;
        T3 += wjk*c1*c1; T4 += wjk*c1*c2; T5 += wjk*c2*c2;
    }
    #pragma unroll
    for (int o = 16; o; o >>= 1) {
        T0 += __shfl_xor_sync(0xffffffffu, T0, o);
        T1 += __shfl_xor_sync(0xffffffffu, T1, o);
        T2 += __shfl_xor_sync(0xffffffffu, T2, o);
        T3 += __shfl_xor_sync(0xffffffffu, T3, o);
        T4 += __shfl_xor_sync(0xffffffffu, T4, o);
        T5 += __shfl_xor_sync(0xffffffffu, T5, o);
    }
    if (lane == 0) {
        atomicAdd(&sT[0], 2.f*T0); atomicAdd(&sT[1], 2.f*T1); atomicAdd(&sT[2], 2.f*T2);
        atomicAdd(&sT[3], 2.f*T3); atomicAdd(&sT[4], 2.f*T4); atomicAdd(&sT[5], 2.f*T5);
    }
    __syncthreads();
    if (t < 6) atomicAdd(&g_tri[b*6 + t], sT[t]);
}

// ---------------- per-batch action update; inv(old cell); zero accumulators ----------------
__global__ void k_action(int is_last, float* __restrict__ out) {
    int b = blockIdx.x;
    if (threadIdx.x != 0) return;
    float s6[6], t6[6];
    #pragma unroll
    for (int i = 0; i < 6; i++) {
        s6[i] = g_strain[b*6+i]; t6[i] = g_tri[b*6+i];
        g_strain[b*6+i] = 0.f;   g_tri[b*6+i] = 0.f;
    }
    const float NK  = (float)(NAT*KNN);
    const float NKK = (float)(NAT*KNN*KNN);
    float P[9];
    P[0] = s6[0]/NK + t6[0]/NKK;
    P[1] = s6[1]/NK + t6[1]/NKK; P[3] = P[1];
    P[2] = s6[2]/NK + t6[2]/NKK; P[6] = P[2];
    P[4] = s6[3]/NK + t6[3]/NKK;
    P[5] = s6[4]/NK + t6[4]/NKK; P[7] = P[5];
    P[8] = s6[5]/NK + t6[5]/NKK;
    float A[9];
    #pragma unroll
    for (int i = 0; i < 9; i++) A[i] = EPSC*P[i] + ((i % 4 == 0) ? 1.f : 0.f);
    float R[9], C[9], Rn[9];
    #pragma unroll
    for (int i = 0; i < 9; i++) { R[i] = g_rho[b*9+i]; C[i] = g_cell[b*9+i]; }
    #pragma unroll
    for (int i = 0; i < 3; i++)
        #pragma unroll
        for (int k = 0; k < 3; k++)
            Rn[i*3+k] = A[i*3+0]*R[0+k] + A[i*3+1]*R[3+k] + A[i*3+2]*R[6+k];
    // inverse of OLD geo_cell (adjugate)
    float det = C[0]*(C[4]*C[8]-C[5]*C[7]) - C[1]*(C[3]*C[8]-C[5]*C[6]) + C[2]*(C[3]*C[7]-C[4]*C[6]);
    float id = 1.f/det;
    float IV[9];
    IV[0]=(C[4]*C[8]-C[5]*C[7])*id;
    IV[1]=(C[2]*C[7]-C[1]*C[8])*id;
    IV[2]=(C[1]*C[5]-C[2]*C[4])*id;
    IV[3]=(C[5]*C[6]-C[3]*C[8])*id;
    IV[4]=(C[0]*C[8]-C[2]*C[6])*id;
    IV[5]=(C[2]*C[3]-C[0]*C[5])*id;
    IV[6]=(C[3]*C[7]-C[4]*C[6])*id;
    IV[7]=(C[1]*C[6]-C[0]*C[7])*id;
    IV[8]=(C[0]*C[4]-C[1]*C[3])*id;
    #pragma unroll
    for (int i = 0; i < 9; i++) {
        g_invcell[b*9+i] = IV[i];
        g_rho[b*9+i] = Rn[i];
        g_cell[b*9+i] = Rn[i];   // geo_cell = rho_prime (cell0 = I)
    }
    if (is_last) {
        #pragma unroll
        for (int i = 0; i < 9; i++) out[NNODE*3 + b*9 + i] = Rn[i];
    }
}

// ---------------- position update: x += x_cart @ inv(old cell); traj += x_cart ----------------
__global__ void k_pos(float* __restrict__ out) {
    int node = blockIdx.x * blockDim.x + threadIdx.x;
    if (node >= NNODE) return;
    int b = node >> 8;
    float xc0 = g_xcart[node*3+0];
    float xc1 = g_xcart[node*3+1];
    float xc2 = g_xcart[node*3+2];
    const float* iv = g_invcell + b*9;
    float xf0 = xc0*iv[0] + xc1*iv[3] + xc2*iv[6];
    float xf1 = xc0*iv[1] + xc1*iv[4] + xc2*iv[7];
    float xf2 = xc0*iv[2] + xc1*iv[5] + xc2*iv[8];
    g_x[node*3+0] += xf0;
    g_x[node*3+1] += xf1;
    g_x[node*3+2] += xf2;
    out[node*3+0] += xc0;
    out[node*3+1] += xc1;
    out[node*3+2] += xc2;
}

// ---------------- launch ----------------
extern "C" void kernel_launch(void* const* d_in, const int* in_sizes, int n_in,
                              void* d_out, int out_size) {
    const float* x_in = (const float*)d_in[1];
    const int*   z    = (const int*)  d_in[2];
    const float* emb  = (const float*)d_in[4];
    const float* mW1  = (const float*)d_in[5];
    const float* mb1  = (const float*)d_in[6];
    const float* mW2  = (const float*)d_in[7];
    const float* mb2  = (const float*)d_in[8];
    const float* uW1  = (const float*)d_in[9];
    const float* ub1  = (const float*)d_in[10];
    const float* uW2  = (const float*)d_in[11];
    const float* ub2  = (const float*)d_in[12];
    const float* awe  = (const float*)d_in[13];
    const float* awp  = (const float*)d_in[14];
    float* out = (float*)d_out;

    const int SZ1 = (FF+1)*FF;

    k_init <<<48, 256>>>(x_in, out);
    k_knn  <<<NNODE, 256>>>();
    k_edges<<<(NEDGE + 255)/256, 256>>>();
    k_mask <<<NNODE, 64>>>();

    k_lin1n<<<NNODE, 128>>>(mW1, mb1, emb, z);
    int p = 0;
    for (int l = 0; l < LL; l++) {
        const float* W1n = (l < 3) ? (mW1 + (l+1)*SZ1) : uW1;
        const float* b1n = (l < 3) ? (mb1 + (l+1)*FF)  : ub1;
        k_fusedL<<<NNODE, 128>>>(mW1 + l*SZ1 + FF*FF, mW2 + l*FF*FF, mb2 + l*FF,
                                 W1n, b1n, (const float*)0, (const float*)0, p);
        p ^= 1;
    }
    for (int l = 0; l < LL; l++) {
        const float* W1n = (l < 3) ? (uW1 + (l+1)*SZ1) : (const float*)0;
        const float* b1n = (l < 3) ? (ub1 + (l+1)*FF)  : (const float*)0;
        k_fusedL<<<NNODE, 128>>>(uW1 + l*SZ1 + FF*FF, uW2 + l*FF*FF, ub2 + l*FF,
                                 W1n, b1n, awe + l*FF, awp + l*FF, p);
        p ^= 1;
        k_edgew<<<NNODE, 128>>>();
        k_action<<<BB, 32>>>(l == LL-1 ? 1 : 0, out);
        k_pos  <<<(NNODE + 255)/256, 256>>>(out);
        if (l < LL-1) k_edges<<<(NEDGE + 255)/256, 256>>>();
    }
}

// round 14
// speedup vs baseline: 1.5988x; 1.2838x over previous
#include <cuda_runtime.h>
#include <math.h>

#define BB 16
#define NAT 256
#define KNN 24
#define FF 128
#define LL 4
#define EPSC 0.01f
#define NNODE (BB*NAT)
#define NEDGE (NNODE*KNN)
#define NPAIR ((KNN*(KNN-1))/2)   // 276 pairs j<k

// ---------------- scratch (device globals; no allocation allowed) ----------------
__device__ float g_x[NNODE*3];
__device__ int   g_idx[NEDGE];
__device__ float g_h[NNODE*FF];
__device__ float g_y[2*NNODE*FF];    // ping-pong per-node W1 transform
__device__ float g_de[NNODE];        // per-node dot(h, act_we)
__device__ float g_dp[NNODE];        // per-node dot(h, actpos_we)
__device__ float g_vec[NEDGE*3];
__device__ float g_dist[NEDGE];
__device__ float g_u[NEDGE*3];
__device__ unsigned char g_mask[NNODE*KNN*KNN];
__device__ uchar2 g_pairs[NPAIR];    // (j,k) with j<k
__device__ float g_xcart[NNODE*3];
__device__ float g_strain[BB*6];   // symmetric 3x3 packed: 00,01,02,11,12,22
__device__ float g_tri[BB*6];
__device__ float g_cell[BB*9];     // geo_cell (row-major)
__device__ float g_rho[BB*9];      // action_rho
__device__ float g_invcell[BB*9];

__constant__ int c_pc[6] = {0,0,0,1,1,2};
__constant__ int c_pd[6] = {0,1,2,1,2,2};

// fast silu: MUFU.EX2-based exp and MUFU.RCP-based divide (few-ulp error, ~1e-7 rel)
__device__ __forceinline__ float siluf(float a) {
    return __fdividef(a, 1.f + __expf(-a));
}

// 128x128 GEMM microkernel: out[t] = sum_f sin[f] * W[f*FF + t]
// Warp w handles f in [32w, 32w+32); lane loads float4 of 4 output columns (LDG.128).
// 4 f-chunk partials combined in chunk order via shared 'red' (512 floats).
// Internally syncs: opening sync makes 'sin' visible and 'red' free; closing sync before read.
__device__ __forceinline__ float gemm128(
    const float* __restrict__ W, const float* sin, float* red, int t)
{
    int lane = t & 31, w = t >> 5;
    __syncthreads();
    float4 a = make_float4(0.f, 0.f, 0.f, 0.f);
    #pragma unroll 8
    for (int f = 0; f < 32; f++) {
        float hv = sin[32*w + f];
        float4 wv = ((const float4*)(W + (32*w + f)*FF))[lane];
        a.x += hv*wv.x; a.y += hv*wv.y; a.z += hv*wv.z; a.w += hv*wv.w;
    }
    ((float4*)(red + w*FF))[lane] = a;
    __syncthreads();
    return red[0*FF + t] + red[1*FF + t] + red[2*FF + t] + red[3*FF + t];
}

// ---------------- init: x = mod(x,1), cells = I, accumulators = 0, traj = 0, pair LUT ------
__global__ void k_init(const float* __restrict__ x_in, float* __restrict__ out) {
    int i = blockIdx.x * blockDim.x + threadIdx.x;
    if (i < NNODE*3) { float v = x_in[i]; g_x[i] = v - floorf(v); out[i] = 0.f; }
    if (i < BB*9) {
        float id = ((i % 9) % 4 == 0) ? 1.f : 0.f;
        g_cell[i] = id; g_rho[i] = id;
    }
    if (i < BB*6) { g_strain[i] = 0.f; g_tri[i] = 0.f; }
    if (i < NPAIR) {
        int r = i, jj = 0;
        while (r >= KNN-1-jj) { r -= KNN-1-jj; jj++; }
        g_pairs[i] = make_uchar2((unsigned char)jj, (unsigned char)(jj+1+r));
    }
}

// ---------------- kNN (periodic min-image, cell = I), exact top_k tie-break ----------------
__global__ void k_knn() {
    int b = blockIdx.x >> 8;
    int i = blockIdx.x & 255;
    __shared__ float sx[NAT*3];
    __shared__ __align__(16) unsigned long long skey[NAT];
    int t = threadIdx.x;
    for (int q = t; q < NAT*3; q += 256) sx[q] = g_x[b*NAT*3 + q];
    __syncthreads();
    float xi0 = sx[i*3+0], xi1 = sx[i*3+1], xi2 = sx[i*3+2];
    float d0 = sx[t*3+0] - xi0; d0 -= rintf(d0);
    float d1 = sx[t*3+1] - xi1; d1 -= rintf(d1);
    float d2 = sx[t*3+2] - xi2; d2 -= rintf(d2);
    float d = sqrtf(d0*d0 + d1*d1 + d2*d2);
    if (t == i) d += 1e6f;
    unsigned long long kt = ((unsigned long long)__float_as_uint(d) << 32) | (unsigned)t;
    skey[t] = kt;
    __syncthreads();
    int rank = 0;
    const ulonglong2* s2 = (const ulonglong2*)skey;
    #pragma unroll 8
    for (int q = 0; q < NAT/2; q++) {
        ulonglong2 v = s2[q];
        rank += (v.x < kt);
        rank += (v.y < kt);
    }
    if (rank < KNN) g_idx[(b*NAT + i)*KNN + rank] = t;
}

// ---------------- initial edge vectors: vec = (frac - round(frac)) @ cell ----------------
__global__ void k_edges() {
    int e = blockIdx.x * blockDim.x + threadIdx.x;
    if (e >= NEDGE) return;
    int b = e / (NAT*KNN);
    int n = (e / KNN) & 255;
    int j = g_idx[e];
    const float* xb = g_x + b*NAT*3;
    float f0 = xb[j*3+0] - xb[n*3+0]; f0 -= rintf(f0);
    float f1 = xb[j*3+1] - xb[n*3+1]; f1 -= rintf(f1);
    float f2 = xb[j*3+2] - xb[n*3+2]; f2 -= rintf(f2);
    const float* C = g_cell + b*9;
    float v0 = f0*C[0] + f1*C[3] + f2*C[6];
    float v1 = f0*C[1] + f1*C[4] + f2*C[7];
    float v2 = f0*C[2] + f1*C[5] + f2*C[8];
    float d  = sqrtf(v0*v0 + v1*v1 + v2*v2);
    g_vec[e*3+0] = v0; g_vec[e*3+1] = v1; g_vec[e*3+2] = v2;
    g_dist[e] = d;
    float inv = 1.f / (d + 1e-12f);
    g_u[e*3+0] = v0*inv; g_u[e*3+1] = v1*inv; g_u[e*3+2] = v2*inv;
}

// ---------------- triplet mask from INITIAL u (fixed thereafter) ----------------
__global__ void k_mask() {
    int node = blockIdx.x;
    __shared__ float su[KNN*3];
    int t = threadIdx.x;  // 64
    if (t < KNN*3) su[t] = g_u[node*KNN*3 + t];
    __syncthreads();
    for (int p = t; p < KNN*KNN; p += 64) {
        int jj = p / KNN, kk = p % KNN;
        const float* a = su + jj*3;
        const float* c = su + kk*3;
        float c0 = a[1]*c[2] - a[2]*c[1];
        float c1 = a[2]*c[0] - a[0]*c[2];
        float c2 = a[0]*c[1] - a[1]*c[0];
        g_mask[node*KNN*KNN + p] = (sqrtf(c0*c0 + c1*c1 + c2*c2) > 1e-3f) ? 1 : 0;
    }
}

// ---------------- first lin1 (per node): h = emb[z]; y = h @ W1[:128,:] + b1 ----------------
__global__ void __launch_bounds__(128) k_lin1n(
    const float* __restrict__ W1, const float* __restrict__ b1,
    const float* __restrict__ emb, const int* __restrict__ z)
{
    int node = blockIdx.x;
    int t = threadIdx.x;
    __shared__ float shh[FF];
    __shared__ float red[4*FF];
    float hv = emb[z[node]*FF + t];
    g_h[node*FF + t] = hv;
    shh[t] = hv;
    float acc = gemm128(W1, shh, red, t) + b1[t];
    g_y[node*FF + t] = acc;
}

// ---------------- fused MPNN layer (per node): aggr -> lin2 -> h += -> lin1(next) ----------
// Reads y from parity p, writes next-layer y to parity p^1 (cross-block race avoided).
// If awe != null, also emits per-node dots de = h·awe, dp = h·awp for the edge-weight kernel.
__global__ void __launch_bounds__(128) k_fusedL(
    const float* __restrict__ wl_row,   // W1 row 128 (dist weights) of current layer
    const float* __restrict__ W2, const float* __restrict__ b2,
    const float* __restrict__ W1n, const float* __restrict__ b1n,
    const float* __restrict__ awe, const float* __restrict__ awp, int p)
{
    int node = blockIdx.x;
    int b = node >> 8;
    int t = threadIdx.x;

    __shared__ float sdist[KNN];
    __shared__ int   sj[KNN];
    __shared__ float shm[FF];
    __shared__ float shh[FF];
    __shared__ float red[4*FF];
    __shared__ float swe[4], swp[4];

    if (t < KNN) { sdist[t] = g_dist[node*KNN + t]; sj[t] = g_idx[node*KNN + t]; }
    __syncthreads();

    // aggr: msum = sum_k silu(y[j_k] + dist_k * wl)
    const float* yb = g_y + p*NNODE*FF + b*NAT*FF;
    float wl = wl_row[t];
    float s = 0.f;
    #pragma unroll 4
    for (int k = 0; k < KNN; k++) {
        float yv = yb[sj[k]*FF + t];
        s += siluf(yv + sdist[k]*wl);
    }
    shm[t] = s;

    // lin2: h += silu(msum @ W2 + b2)   (gemm128 syncs internally)
    float acc = gemm128(W2, shm, red, t) + b2[t];
    float hn = g_h[node*FF + t] + siluf(acc);
    g_h[node*FF + t] = hn;
    shh[t] = hn;

    // per-node action dots (used by k_edgew: w_e = tanh(de_i + de_j))
    if (awe) {
        float re = hn * awe[t];
        float rp = hn * awp[t];
        #pragma unroll
        for (int o = 16; o; o >>= 1) {
            re += __shfl_xor_sync(0xffffffffu, re, o);
            rp += __shfl_xor_sync(0xffffffffu, rp, o);
        }
        if ((t & 31) == 0) { swe[t >> 5] = re; swp[t >> 5] = rp; }
        __syncthreads();
        if (t == 0) {
            g_de[node] = swe[0] + swe[1] + swe[2] + swe[3];
            g_dp[node] = swp[0] + swp[1] + swp[2] + swp[3];
        }
    }

    // lin1 of next layer (node-local h; gemm128 opening sync protects shh and red)
    if (W1n) {
        float a1 = gemm128(W1n, shh, red, t) + b1n[t];
        g_y[(p^1)*NNODE*FF + node*FF + t] = a1;
    }
}

// ---------------- edge weights (from precomputed dots) + strain/tri + x_cart ----------------
__global__ void __launch_bounds__(128) k_edgew()
{
    int node = blockIdx.x;
    int b = node >> 8;
    int t = threadIdx.x;
    int lane = t & 31;

    __shared__ float sh_we[KNN], sh_wp[KNN];
    __shared__ float su[KNN*3], sv[KNN*3];
    __shared__ float sT[6];

    if (t < KNN*3) { su[t] = g_u[node*KNN*3 + t]; sv[t] = g_vec[node*KNN*3 + t]; }
    if (t < KNN) {
        int j = g_idx[node*KNN + t];
        sh_we[t] = tanhf(g_de[node] + g_de[b*NAT + j]);
        sh_wp[t] = tanhf(g_dp[node] + g_dp[b*NAT + j]);
    }
    if (t < 6) sT[t] = 0.f;
    __syncthreads();

    // strain partial (symmetric 6) and x_cart
    if (t < 6) {
        int c = c_pc[t], d = c_pd[t];
        float s = 0.f;
        #pragma unroll
        for (int k = 0; k < KNN; k++) s += sh_we[k] * su[k*3+c] * su[k*3+d];
        atomicAdd(&g_strain[b*6 + t], s);
    } else if (t >= 16 && t < 19) {
        int c = t - 16;
        float s = 0.f;
        #pragma unroll
        for (int k = 0; k < KNN; k++) s += sh_wp[k] * sv[k*3+c];
        g_xcart[node*3 + c] = EPSC * s;
    }

    // tri partial: symmetric in (j,k), diagonal always masked -> 2 * sum over j<k (276 pairs)
    float T0=0.f,T1=0.f,T2=0.f,T3=0.f,T4=0.f,T5=0.f;
    const unsigned char* mp = g_mask + node*KNN*KNN;
    for (int q = t; q < NPAIR; q += 128) {
        uchar2 pr = g_pairs[q];
        int jj = pr.x, kk = pr.y;
        if (!mp[jj*KNN + kk]) continue;
        float wjk = sh_we[jj] * sh_we[kk];
        const float* a = su + jj*3;
        const float* c = su + kk*3;
        float c0 = a[1]*c[2] - a[2]*c[1];
        float c1 = a[2]*c[0] - a[0]*c[2];
        float c2 = a[0]*c[1] - a[1]*c[0];
        T0 += wjk*c0*c0; T1 += wjk*c0*c1; T2 += wjk*c0*c2;
        T3 += wjk*c1*c1; T4 += wjk*c1*c2; T5 += wjk*c2*c2;
    }
    #pragma unroll
    for (int o = 16; o; o >>= 1) {
        T0 += __shfl_xor_sync(0xffffffffu, T0, o);
        T1 += __shfl_xor_sync(0xffffffffu, T1, o);
        T2 += __shfl_xor_sync(0xffffffffu, T2, o);
        T3 += __shfl_xor_sync(0xffffffffu, T3, o);
        T4 += __shfl_xor_sync(0xffffffffu, T4, o);
        T5 += __shfl_xor_sync(0xffffffffu, T5, o);
    }
    if (lane == 0) {
        atomicAdd(&sT[0], 2.f*T0); atomicAdd(&sT[1], 2.f*T1); atomicAdd(&sT[2], 2.f*T2);
        atomicAdd(&sT[3], 2.f*T3); atomicAdd(&sT[4], 2.f*T4); atomicAdd(&sT[5], 2.f*T5);
    }
    __syncthreads();
    if (t < 6) atomicAdd(&g_tri[b*6 + t], sT[t]);
}

// ---------------- per-batch action update; inv(old cell); zero accumulators ----------------
__global__ void k_action(int is_last, float* __restrict__ out) {
    int b = blockIdx.x;
    if (threadIdx.x != 0) return;
    float s6[6], t6[6];
    #pragma unroll
    for (int i = 0; i < 6; i++) {
        s6[i] = g_strain[b*6+i]; t6[i] = g_tri[b*6+i];
        g_strain[b*6+i] = 0.f;   g_tri[b*6+i] = 0.f;
    }
    const float NK  = (float)(NAT*KNN);
    const float NKK = (float)(NAT*KNN*KNN);
    float P[9];
    P[0] = s6[0]/NK + t6[0]/NKK;
    P[1] = s6[1]/NK + t6[1]/NKK; P[3] = P[1];
    P[2] = s6[2]/NK + t6[2]/NKK; P[6] = P[2];
    P[4] = s6[3]/NK + t6[3]/NKK;
    P[5] = s6[4]/NK + t6[4]/NKK; P[7] = P[5];
    P[8] = s6[5]/NK + t6[5]/NKK;
    float A[9];
    #pragma unroll
    for (int i = 0; i < 9; i++) A[i] = EPSC*P[i] + ((i % 4 == 0) ? 1.f : 0.f);
    float R[9], C[9], Rn[9];
    #pragma unroll
    for (int i = 0; i < 9; i++) { R[i] = g_rho[b*9+i]; C[i] = g_cell[b*9+i]; }
    #pragma unroll
    for (int i = 0; i < 3; i++)
        #pragma unroll
        for (int k = 0; k < 3; k++)
            Rn[i*3+k] = A[i*3+0]*R[0+k] + A[i*3+1]*R[3+k] + A[i*3+2]*R[6+k];
    // inverse of OLD geo_cell (adjugate)
    float det = C[0]*(C[4]*C[8]-C[5]*C[7]) - C[1]*(C[3]*C[8]-C[5]*C[6]) + C[2]*(C[3]*C[7]-C[4]*C[6]);
    float id = 1.f/det;
    float IV[9];
    IV[0]=(C[4]*C[8]-C[5]*C[7])*id;
    IV[1]=(C[2]*C[7]-C[1]*C[8])*id;
    IV[2]=(C[1]*C[5]-C[2]*C[4])*id;
    IV[3]=(C[5]*C[6]-C[3]*C[8])*id;
    IV[4]=(C[0]*C[8]-C[2]*C[6])*id;
    IV[5]=(C[2]*C[3]-C[0]*C[5])*id;
    IV[6]=(C[3]*C[7]-C[4]*C[6])*id;
    IV[7]=(C[1]*C[6]-C[0]*C[7])*id;
    IV[8]=(C[0]*C[4]-C[1]*C[3])*id;
    #pragma unroll
    for (int i = 0; i < 9; i++) {
        g_invcell[b*9+i] = IV[i];
        g_rho[b*9+i] = Rn[i];
        g_cell[b*9+i] = Rn[i];   // geo_cell = rho_prime (cell0 = I)
    }
    if (is_last) {
        #pragma unroll
        for (int i = 0; i < 9; i++) out[NNODE*3 + b*9 + i] = Rn[i];
    }
}

// ---------------- position update: x += x_cart @ inv(old cell); traj += x_cart ----------------
__global__ void k_pos(float* __restrict__ out) {
    int node = blockIdx.x * blockDim.x + threadIdx.x;
    if (node >= NNODE) return;
    int b = node >> 8;
    float xc0 = g_xcart[node*3+0];
    float xc1 = g_xcart[node*3+1];
    float xc2 = g_xcart[node*3+2];
    const float* iv = g_invcell + b*9;
    float xf0 = xc0*iv[0] + xc1*iv[3] + xc2*iv[6];
    float xf1 = xc0*iv[1] + xc1*iv[4] + xc2*iv[7];
    float xf2 = xc0*iv[2] + xc1*iv[5] + xc2*iv[8];
    g_x[node*3+0] += xf0;
    g_x[node*3+1] += xf1;
    g_x[node*3+2] += xf2;
    out[node*3+0] += xc0;
    out[node*3+1] += xc1;
    out[node*3+2] += xc2;
}

// ---------------- launch ----------------
extern "C" void kernel_launch(void* const* d_in, const int* in_sizes, int n_in,
                              void* d_out, int out_size) {
    const float* x_in = (const float*)d_in[1];
    const int*   z    = (const int*)  d_in[2];
    const float* emb  = (const float*)d_in[4];
    const float* mW1  = (const float*)d_in[5];
    const float* mb1  = (const float*)d_in[6];
    const float* mW2  = (const float*)d_in[7];
    const float* mb2  = (const float*)d_in[8];
    const float* uW1  = (const float*)d_in[9];
    const float* ub1  = (const float*)d_in[10];
    const float* uW2  = (const float*)d_in[11];
    const float* ub2  = (const float*)d_in[12];
    const float* awe  = (const float*)d_in[13];
    const float* awp  = (const float*)d_in[14];
    float* out = (float*)d_out;

    const int SZ1 = (FF+1)*FF;

    k_init <<<48, 256>>>(x_in, out);
    k_knn  <<<NNODE, 256>>>();
    k_edges<<<(NEDGE + 255)/256, 256>>>();
    k_mask <<<NNODE, 64>>>();

    k_lin1n<<<NNODE, 128>>>(mW1, mb1, emb, z);
    int p = 0;
    for (int l = 0; l < LL; l++) {
        const float* W1n = (l < 3) ? (mW1 + (l+1)*SZ1) : uW1;
        const float* b1n = (l < 3) ? (mb1 + (l+1)*FF)  : ub1;
        k_fusedL<<<NNODE, 128>>>(mW1 + l*SZ1 + FF*FF, mW2 + l*FF*FF, mb2 + l*FF,
                                 W1n, b1n, (const float*)0, (const float*)0, p);
        p ^= 1;
    }
    for (int l = 0; l < LL; l++) {
        const float* W1n = (l < 3) ? (uW1 + (l+1)*SZ1) : (const float*)0;
        const float* b1n = (l < 3) ? (ub1 + (l+1)*FF)  : (const float*)0;
        k_fusedL<<<NNODE, 128>>>(uW1 + l*SZ1 + FF*FF, uW2 + l*FF*FF, ub2 + l*FF,
                                 W1n, b1n, awe + l*FF, awp + l*FF, p);
        p ^= 1;
        k_edgew<<<NNODE, 128>>>();
        k_action<<<BB, 32>>>(l == LL-1 ? 1 : 0, out);
        k_pos  <<<(NNODE + 255)/256, 256>>>(out);
        if (l < LL-1) k_edges<<<(NEDGE + 255)/256, 256>>>();
    }
}

// round 15
// speedup vs baseline: 1.9264x; 1.2049x over previous
#include <cuda_runtime.h>
#include <math.h>

#define BB 16
#define NAT 256
#define KNN 24
#define FF 128
#define LL 4
#define EPSC 0.01f
#define NNODE (BB*NAT)
#define NEDGE (NNODE*KNN)
#define NPAIR ((KNN*(KNN-1))/2)   // 276 pairs j<k

// ---------------- scratch (device globals; no allocation allowed) ----------------
__device__ float g_x[NNODE*3];
__device__ int   g_idx[NEDGE];
__device__ float g_h[NNODE*FF];
__device__ float g_y[2*NNODE*FF];    // ping-pong per-node W1 transform
__device__ float g_de[NNODE];        // per-node dot(h, act_we)
__device__ float g_dp[NNODE];        // per-node dot(h, actpos_we)
__device__ float g_vec[NEDGE*3];
__device__ float g_dist[NEDGE];
__device__ float g_u[NEDGE*3];
__device__ unsigned char g_mask[NNODE*KNN*KNN];
__device__ uchar2 g_pairs[NPAIR];    // (j,k) with j<k
__device__ float g_xcart[NNODE*3];
__device__ float g_strain[BB*6];   // symmetric 3x3 packed: 00,01,02,11,12,22
__device__ float g_tri[BB*6];
__device__ float g_cell[BB*9];     // geo_cell (row-major)
__device__ float g_rho[BB*9];      // action_rho

__constant__ int c_pc[6] = {0,0,0,1,1,2};
__constant__ int c_pd[6] = {0,1,2,1,2,2};

// fast silu / tanh via MUFU (few-ulp error; tanh saturates correctly at +/-inf)
__device__ __forceinline__ float siluf(float a) {
    return __fdividef(a, 1.f + __expf(-a));
}
__device__ __forceinline__ float tanhfast(float x) {
    return 1.f - __fdividef(2.f, __expf(2.f*x) + 1.f);
}

// 128x128 GEMM on TWO input vectors sharing weight loads:
// out_i[t] = sum_f s_i[f] * W[f*FF + t].  Warp w owns f in [32w,32w+32);
// lane loads float4 of 4 output columns once, FMAs against both nodes.
// red is 8*FF floats. Internally syncs (opening + closing).
__device__ __forceinline__ void gemm128x2(
    const float* __restrict__ W, const float* s0, const float* s1,
    float* red, int t, float* o0, float* o1)
{
    int lane = t & 31, w = t >> 5;
    __syncthreads();
    float4 a0 = make_float4(0.f,0.f,0.f,0.f);
    float4 a1 = make_float4(0.f,0.f,0.f,0.f);
    #pragma unroll 8
    for (int f = 0; f < 32; f++) {
        float h0 = s0[32*w + f];
        float h1 = s1[32*w + f];
        float4 wv = ((const float4*)(W + (32*w + f)*FF))[lane];
        a0.x += h0*wv.x; a0.y += h0*wv.y; a0.z += h0*wv.z; a0.w += h0*wv.w;
        a1.x += h1*wv.x; a1.y += h1*wv.y; a1.z += h1*wv.z; a1.w += h1*wv.w;
    }
    ((float4*)(red + w*FF))[lane] = a0;
    ((float4*)(red + (4+w)*FF))[lane] = a1;
    __syncthreads();
    *o0 = red[0*FF + t] + red[1*FF + t] + red[2*FF + t] + red[3*FF + t];
    *o1 = red[4*FF + t] + red[5*FF + t] + red[6*FF + t] + red[7*FF + t];
}

// ---------------- init: x = mod(x,1), cells = I, accumulators = 0, traj = 0, pair LUT ------
__global__ void k_init(const float* __restrict__ x_in, float* __restrict__ out) {
    int i = blockIdx.x * blockDim.x + threadIdx.x;
    if (i < NNODE*3) { float v = x_in[i]; g_x[i] = v - floorf(v); out[i] = 0.f; }
    if (i < BB*9) {
        float id = ((i % 9) % 4 == 0) ? 1.f : 0.f;
        g_cell[i] = id; g_rho[i] = id;
    }
    if (i < BB*6) { g_strain[i] = 0.f; g_tri[i] = 0.f; }
    if (i < NPAIR) {
        int r = i, jj = 0;
        while (r >= KNN-1-jj) { r -= KNN-1-jj; jj++; }
        g_pairs[i] = make_uchar2((unsigned char)jj, (unsigned char)(jj+1+r));
    }
}

// ---------------- kNN (periodic min-image, cell = I), exact top_k tie-break ----------------
__global__ void k_knn() {
    int b = blockIdx.x >> 8;
    int i = blockIdx.x & 255;
    __shared__ float sx[NAT*3];
    __shared__ __align__(16) unsigned long long skey[NAT];
    int t = threadIdx.x;
    for (int q = t; q < NAT*3; q += 256) sx[q] = g_x[b*NAT*3 + q];
    __syncthreads();
    float xi0 = sx[i*3+0], xi1 = sx[i*3+1], xi2 = sx[i*3+2];
    float d0 = sx[t*3+0] - xi0; d0 -= rintf(d0);
    float d1 = sx[t*3+1] - xi1; d1 -= rintf(d1);
    float d2 = sx[t*3+2] - xi2; d2 -= rintf(d2);
    float d = sqrtf(d0*d0 + d1*d1 + d2*d2);
    if (t == i) d += 1e6f;
    unsigned long long kt = ((unsigned long long)__float_as_uint(d) << 32) | (unsigned)t;
    skey[t] = kt;
    __syncthreads();
    int rank = 0;
    const ulonglong2* s2 = (const ulonglong2*)skey;
    #pragma unroll 8
    for (int q = 0; q < NAT/2; q++) {
        ulonglong2 v = s2[q];
        rank += (v.x < kt);
        rank += (v.y < kt);
    }
    if (rank < KNN) g_idx[(b*NAT + i)*KNN + rank] = t;
}

// ---------------- edge vectors: vec = (frac - round(frac)) @ cell ----------------
__global__ void k_edges() {
    int e = blockIdx.x * blockDim.x + threadIdx.x;
    if (e >= NEDGE) return;
    int b = e / (NAT*KNN);
    int n = (e / KNN) & 255;
    int j = g_idx[e];
    const float* xb = g_x + b*NAT*3;
    float f0 = xb[j*3+0] - xb[n*3+0]; f0 -= rintf(f0);
    float f1 = xb[j*3+1] - xb[n*3+1]; f1 -= rintf(f1);
    float f2 = xb[j*3+2] - xb[n*3+2]; f2 -= rintf(f2);
    const float* C = g_cell + b*9;
    float v0 = f0*C[0] + f1*C[3] + f2*C[6];
    float v1 = f0*C[1] + f1*C[4] + f2*C[7];
    float v2 = f0*C[2] + f1*C[5] + f2*C[8];
    float d  = sqrtf(v0*v0 + v1*v1 + v2*v2);
    g_vec[e*3+0] = v0; g_vec[e*3+1] = v1; g_vec[e*3+2] = v2;
    g_dist[e] = d;
    float inv = 1.f / (d + 1e-12f);
    g_u[e*3+0] = v0*inv; g_u[e*3+1] = v1*inv; g_u[e*3+2] = v2*inv;
}

// ---------------- triplet mask from INITIAL u (fixed thereafter) ----------------
__global__ void k_mask() {
    int node = blockIdx.x;
    __shared__ float su[KNN*3];
    int t = threadIdx.x;  // 64
    if (t < KNN*3) su[t] = g_u[node*KNN*3 + t];
    __syncthreads();
    for (int p = t; p < KNN*KNN; p += 64) {
        int jj = p / KNN, kk = p % KNN;
        const float* a = su + jj*3;
        const float* c = su + kk*3;
        float c0 = a[1]*c[2] - a[2]*c[1];
        float c1 = a[2]*c[0] - a[0]*c[2];
        float c2 = a[0]*c[1] - a[1]*c[0];
        g_mask[node*KNN*KNN + p] = (sqrtf(c0*c0 + c1*c1 + c2*c2) > 1e-3f) ? 1 : 0;
    }
}

// ---------------- first lin1 (2 nodes/block): h = emb[z]; y = h @ W1[:128,:] + b1 ----------
__global__ void __launch_bounds__(128) k_lin1n(
    const float* __restrict__ W1, const float* __restrict__ b1,
    const float* __restrict__ emb, const int* __restrict__ z)
{
    int n0 = blockIdx.x * 2;
    int t = threadIdx.x;
    __shared__ float sh0[FF], sh1[FF];
    __shared__ float red[8*FF];
    float h0 = emb[z[n0]*FF + t];
    float h1 = emb[z[n0+1]*FF + t];
    g_h[n0*FF + t] = h0;
    g_h[(n0+1)*FF + t] = h1;
    sh0[t] = h0; sh1[t] = h1;
    float a0, a1;
    gemm128x2(W1, sh0, sh1, red, t, &a0, &a1);
    float bg = b1[t];
    g_y[n0*FF + t] = a0 + bg;
    g_y[(n0+1)*FF + t] = a1 + bg;
}

// ---------------- fused MPNN layer (2 nodes/block): aggr -> lin2 -> h += -> lin1(next) -----
// Reads y from parity p, writes next-layer y to parity p^1.
__global__ void __launch_bounds__(128) k_fusedL(
    const float* __restrict__ wl_row,   // W1 row 128 (dist weights) of current layer
    const float* __restrict__ W2, const float* __restrict__ b2,
    const float* __restrict__ W1n, const float* __restrict__ b1n,
    const float* __restrict__ awe, const float* __restrict__ awp, int p)
{
    int n0 = blockIdx.x * 2;
    int b = n0 >> 8;
    int t = threadIdx.x;

    __shared__ float sdist[2*KNN];
    __shared__ int   sj[2*KNN];
    __shared__ float shm0[FF], shm1[FF];
    __shared__ float shh0[FF], shh1[FF];
    __shared__ float red[8*FF];
    __shared__ float swe[8], swp[8];

    if (t < 2*KNN) { sdist[t] = g_dist[n0*KNN + t]; sj[t] = g_idx[n0*KNN + t]; }
    __syncthreads();

    // aggr for both nodes: msum = sum_k silu(y[j_k] + dist_k * wl)
    const float* yb = g_y + p*NNODE*FF + b*NAT*FF;
    float wl = wl_row[t];
    float s0 = 0.f, s1 = 0.f;
    #pragma unroll 4
    for (int k = 0; k < KNN; k++) {
        s0 += siluf(yb[sj[k]*FF + t]       + sdist[k]*wl);
        s1 += siluf(yb[sj[KNN+k]*FF + t]   + sdist[KNN+k]*wl);
    }
    shm0[t] = s0; shm1[t] = s1;

    // lin2 both nodes (shared weight loads)
    float a0, a1;
    gemm128x2(W2, shm0, shm1, red, t, &a0, &a1);
    float bg = b2[t];
    float hn0 = g_h[n0*FF + t]     + siluf(a0 + bg);
    float hn1 = g_h[(n0+1)*FF + t] + siluf(a1 + bg);
    g_h[n0*FF + t] = hn0;
    g_h[(n0+1)*FF + t] = hn1;

    // per-node action dots (w_e = tanh(de_i + de_j) downstream)
    if (awe) {
        float ae = awe[t], ap = awp[t];
        float re0 = hn0*ae, rp0 = hn0*ap, re1 = hn1*ae, rp1 = hn1*ap;
        #pragma unroll
        for (int o = 16; o; o >>= 1) {
            re0 += __shfl_xor_sync(0xffffffffu, re0, o);
            rp0 += __shfl_xor_sync(0xffffffffu, rp0, o);
            re1 += __shfl_xor_sync(0xffffffffu, re1, o);
            rp1 += __shfl_xor_sync(0xffffffffu, rp1, o);
        }
        int w = t >> 5;
        if ((t & 31) == 0) { swe[w] = re0; swp[w] = rp0; swe[4+w] = re1; swp[4+w] = rp1; }
        __syncthreads();
        if (t == 0) {
            g_de[n0]   = swe[0]+swe[1]+swe[2]+swe[3];
            g_dp[n0]   = swp[0]+swp[1]+swp[2]+swp[3];
            g_de[n0+1] = swe[4]+swe[5]+swe[6]+swe[7];
            g_dp[n0+1] = swp[4]+swp[5]+swp[6]+swp[7];
        }
    }

    // lin1 of next layer (node-local h; gemm opening sync protects shh/red)
    if (W1n) {
        shh0[t] = hn0; shh1[t] = hn1;
        float y0, y1;
        gemm128x2(W1n, shh0, shh1, red, t, &y0, &y1);
        float bg1 = b1n[t];
        g_y[(p^1)*NNODE*FF + n0*FF + t]     = y0 + bg1;
        g_y[(p^1)*NNODE*FF + (n0+1)*FF + t] = y1 + bg1;
    }
}

// ---------------- edge weights (from precomputed dots) + strain/tri + x_cart ----------------
__global__ void __launch_bounds__(128) k_edgew()
{
    int node = blockIdx.x;
    int b = node >> 8;
    int t = threadIdx.x;
    int lane = t & 31;

    __shared__ float sh_we[KNN], sh_wp[KNN];
    __shared__ float su[KNN*3], sv[KNN*3];
    __shared__ float sT[6];

    if (t < KNN*3) { su[t] = g_u[node*KNN*3 + t]; sv[t] = g_vec[node*KNN*3 + t]; }
    if (t < KNN) {
        int j = g_idx[node*KNN + t];
        sh_we[t] = tanhfast(g_de[node] + g_de[b*NAT + j]);
        sh_wp[t] = tanhfast(g_dp[node] + g_dp[b*NAT + j]);
    }
    if (t < 6) sT[t] = 0.f;
    __syncthreads();

    // strain partial (symmetric 6) and x_cart
    if (t < 6) {
        int c = c_pc[t], d = c_pd[t];
        float s = 0.f;
        #pragma unroll
        for (int k = 0; k < KNN; k++) s += sh_we[k] * su[k*3+c] * su[k*3+d];
        atomicAdd(&g_strain[b*6 + t], s);
    } else if (t >= 16 && t < 19) {
        int c = t - 16;
        float s = 0.f;
        #pragma unroll
        for (int k = 0; k < KNN; k++) s += sh_wp[k] * sv[k*3+c];
        g_xcart[node*3 + c] = EPSC * s;
    }

    // tri partial: symmetric in (j,k), diagonal always masked -> 2 * sum over j<k (276 pairs)
    float T0=0.f,T1=0.f,T2=0.f,T3=0.f,T4=0.f,T5=0.f;
    const unsigned char* mp = g_mask + node*KNN*KNN;
    for (int q = t; q < NPAIR; q += 128) {
        uchar2 pr = g_pairs[q];
        int jj = pr.x, kk = pr.y;
        if (!mp[jj*KNN + kk]) continue;
        float wjk = sh_we[jj] * sh_we[kk];
        const float* a = su + jj*3;
        const float* c = su + kk*3;
        float c0 = a[1]*c[2] - a[2]*c[1];
        float c1 = a[2]*c[0] - a[0]*c[2];
        float c2 = a[0]*c[1] - a[1]*c[0];
        T0 += wjk*c0*c0; T1 += wjk*c0*c1; T2 += wjk*c0*c2;
        T3 += wjk*c1*c1; T4 += wjk*c1*c2; T5 += wjk*c2*c2;
    }
    #pragma unroll
    for (int o = 16; o; o >>= 1) {
        T0 += __shfl_xor_sync(0xffffffffu, T0, o);
        T1 += __shfl_xor_sync(0xffffffffu, T1, o);
        T2 += __shfl_xor_sync(0xffffffffu, T2, o);
        T3 += __shfl_xor_sync(0xffffffffu, T3, o);
        T4 += __shfl_xor_sync(0xffffffffu, T4, o);
        T5 += __shfl_xor_sync(0xffffffffu, T5, o);
    }
    if (lane == 0) {
        atomicAdd(&sT[0], 2.f*T0); atomicAdd(&sT[1], 2.f*T1); atomicAdd(&sT[2], 2.f*T2);
        atomicAdd(&sT[3], 2.f*T3); atomicAdd(&sT[4], 2.f*T4); atomicAdd(&sT[5], 2.f*T5);
    }
    __syncthreads();
    if (t < 6) atomicAdd(&g_tri[b*6 + t], sT[t]);
}

// ---------------- fused action + position update (one block per batch, 256 threads) --------
__global__ void __launch_bounds__(256) k_acpos(int is_last, float* __restrict__ out)
{
    int b = blockIdx.x;
    int t = threadIdx.x;
    __shared__ float s_iv[9];

    if (t == 0) {
        float s6[6], t6[6];
        #pragma unroll
        for (int i = 0; i < 6; i++) {
            s6[i] = g_strain[b*6+i]; t6[i] = g_tri[b*6+i];
            g_strain[b*6+i] = 0.f;   g_tri[b*6+i] = 0.f;
        }
        const float NK  = (float)(NAT*KNN);
        const float NKK = (float)(NAT*KNN*KNN);
        float P[9];
        P[0] = s6[0]/NK + t6[0]/NKK;
        P[1] = s6[1]/NK + t6[1]/NKK; P[3] = P[1];
        P[2] = s6[2]/NK + t6[2]/NKK; P[6] = P[2];
        P[4] = s6[3]/NK + t6[3]/NKK;
        P[5] = s6[4]/NK + t6[4]/NKK; P[7] = P[5];
        P[8] = s6[5]/NK + t6[5]/NKK;
        float A[9];
        #pragma unroll
        for (int i = 0; i < 9; i++) A[i] = EPSC*P[i] + ((i % 4 == 0) ? 1.f : 0.f);
        float R[9], C[9], Rn[9];
        #pragma unroll
        for (int i = 0; i < 9; i++) { R[i] = g_rho[b*9+i]; C[i] = g_cell[b*9+i]; }
        #pragma unroll
        for (int i = 0; i < 3; i++)
            #pragma unroll
            for (int k = 0; k < 3; k++)
                Rn[i*3+k] = A[i*3+0]*R[0+k] + A[i*3+1]*R[3+k] + A[i*3+2]*R[6+k];
        // inverse of OLD geo_cell (adjugate)
        float det = C[0]*(C[4]*C[8]-C[5]*C[7]) - C[1]*(C[3]*C[8]-C[5]*C[6]) + C[2]*(C[3]*C[7]-C[4]*C[6]);
        float id = 1.f/det;
        s_iv[0]=(C[4]*C[8]-C[5]*C[7])*id;
        s_iv[1]=(C[2]*C[7]-C[1]*C[8])*id;
        s_iv[2]=(C[1]*C[5]-C[2]*C[4])*id;
        s_iv[3]=(C[5]*C[6]-C[3]*C[8])*id;
        s_iv[4]=(C[0]*C[8]-C[2]*C[6])*id;
        s_iv[5]=(C[2]*C[3]-C[0]*C[5])*id;
        s_iv[6]=(C[3]*C[7]-C[4]*C[6])*id;
        s_iv[7]=(C[1]*C[6]-C[0]*C[7])*id;
        s_iv[8]=(C[0]*C[4]-C[1]*C[3])*id;
        #pragma unroll
        for (int i = 0; i < 9; i++) {
            g_rho[b*9+i] = Rn[i];
            g_cell[b*9+i] = Rn[i];   // geo_cell = rho_prime (cell0 = I)
        }
        if (is_last) {
            #pragma unroll
            for (int i = 0; i < 9; i++) out[NNODE*3 + b*9 + i] = Rn[i];
        }
    }
    __syncthreads();

    int node = b*NAT + t;
    float xc0 = g_xcart[node*3+0];
    float xc1 = g_xcart[node*3+1];
    float xc2 = g_xcart[node*3+2];
    float xf0 = xc0*s_iv[0] + xc1*s_iv[3] + xc2*s_iv[6];
    float xf1 = xc0*s_iv[1] + xc1*s_iv[4] + xc2*s_iv[7];
    float xf2 = xc0*s_iv[2] + xc1*s_iv[5] + xc2*s_iv[8];
    g_x[node*3+0] += xf0;
    g_x[node*3+1] += xf1;
    g_x[node*3+2] += xf2;
    out[node*3+0] += xc0;
    out[node*3+1] += xc1;
    out[node*3+2] += xc2;
}

// ---------------- launch ----------------
extern "C" void kernel_launch(void* const* d_in, const int* in_sizes, int n_in,
                              void* d_out, int out_size) {
    const float* x_in = (const float*)d_in[1];
    const int*   z    = (const int*)  d_in[2];
    const float* emb  = (const float*)d_in[4];
    const float* mW1  = (const float*)d_in[5];
    const float* mb1  = (const float*)d_in[6];
    const float* mW2  = (const float*)d_in[7];
    const float* mb2  = (const float*)d_in[8];
    const float* uW1  = (const float*)d_in[9];
    const float* ub1  = (const float*)d_in[10];
    const float* uW2  = (const float*)d_in[11];
    const float* ub2  = (const float*)d_in[12];
    const float* awe  = (const float*)d_in[13];
    const float* awp  = (const float*)d_in[14];
    float* out = (float*)d_out;

    const int SZ1 = (FF+1)*FF;

    k_init <<<48, 256>>>(x_in, out);
    k_knn  <<<NNODE, 256>>>();
    k_edges<<<(NEDGE + 255)/256, 256>>>();
    k_mask <<<NNODE, 64>>>();

    k_lin1n<<<NNODE/2, 128>>>(mW1, mb1, emb, z);
    int p = 0;
    for (int l = 0; l < LL; l++) {
        const float* W1n = (l < 3) ? (mW1 + (l+1)*SZ1) : uW1;
        const float* b1n = (l < 3) ? (mb1 + (l+1)*FF)  : ub1;
        k_fusedL<<<NNODE/2, 128>>>(mW1 + l*SZ1 + FF*FF, mW2 + l*FF*FF, mb2 + l*FF,
                                   W1n, b1n, (const float*)0, (const float*)0, p);
        p ^= 1;
    }
    for (int l = 0; l < LL; l++) {
        const float* W1n = (l < 3) ? (uW1 + (l+1)*SZ1) : (const float*)0;
        const float* b1n = (l < 3) ? (ub1 + (l+1)*FF)  : (const float*)0;
        k_fusedL<<<NNODE/2, 128>>>(uW1 + l*SZ1 + FF*FF, uW2 + l*FF*FF, ub2 + l*FF,
                                   W1n, b1n, awe + l*FF, awp + l*FF, p);
        p ^= 1;
        k_edgew<<<NNODE, 128>>>();
        k_acpos<<<BB, 256>>>(l == LL-1 ? 1 : 0, out);
        if (l < LL-1) k_edges<<<(NEDGE + 255)/256, 256>>>();
    }
}